// round 8
// baseline (speedup 1.0000x reference)
#include <cuda_runtime.h>
#include <cuda_bf16.h>
#include <cstdint>

#define B_  4
#define S_  1024
#define D_  2048
#define H_  16
#define HD_ 128

#define MA_ (B_*S_)    // 4096
#define NA_ (3*D_)     // 6144
#define KA_ D_         // 2048

// Scratch (allocation-free rule)
__device__ float g_q[B_*H_*S_*HD_];
__device__ float g_k[B_*H_*S_*HD_];
__device__ float g_v[B_*H_*S_*HD_];
__device__ __align__(16) __nv_bfloat16 g_ah[(size_t)MA_*KA_];
__device__ __align__(16) __nv_bfloat16 g_al[(size_t)MA_*KA_];
__device__ __align__(16) __nv_bfloat16 g_wh[(size_t)NA_*KA_];
__device__ __align__(16) __nv_bfloat16 g_wl[(size_t)NA_*KA_];
__device__ int g_bad;

__device__ __forceinline__ void mma_bf16(float c[4], const uint32_t a[4],
                                         const uint32_t b[2]) {
    asm volatile("mma.sync.aligned.m16n8k16.row.col.f32.bf16.bf16.f32 "
        "{%0,%1,%2,%3}, {%4,%5,%6,%7}, {%8,%9}, {%0,%1,%2,%3};"
        : "+f"(c[0]), "+f"(c[1]), "+f"(c[2]), "+f"(c[3])
        : "r"(a[0]), "r"(a[1]), "r"(a[2]), "r"(a[3]), "r"(b[0]), "r"(b[1]));
}

// ---------------------------------------------------------------------------
// Flag reset + MMA probe: verify instruction + fragment model on known data.
// ---------------------------------------------------------------------------
__global__ void reset_flag() { g_bad = 0; }

__global__ void probe_mma() {
    __shared__ __nv_bfloat16 pA[16*16];   // A[16][16] row-major (m,k)
    __shared__ __nv_bfloat16 pB[8*16];    // W[8][16]  row-major (n,k)
    int lid = threadIdx.x;
    for (int i = lid; i < 256; i += 32)
        pA[i] = __float2bfloat16_rn(((i*7 + 3) % 31 - 15) * 0.03f);
    for (int i = lid; i < 128; i += 32)
        pB[i] = __float2bfloat16_rn(((i*11 + 5) % 29 - 14) * 0.05f);
    __syncwarp();

    int qr = lid >> 2, kp = (lid & 3) * 2;
    uint32_t a[4], b[2];
    a[0] = *(const uint32_t*)&pA[qr*16 + kp];
    a[1] = *(const uint32_t*)&pA[(qr+8)*16 + kp];
    a[2] = *(const uint32_t*)&pA[qr*16 + kp + 8];
    a[3] = *(const uint32_t*)&pA[(qr+8)*16 + kp + 8];
    b[0] = *(const uint32_t*)&pB[qr*16 + kp];
    b[1] = *(const uint32_t*)&pB[qr*16 + kp + 8];
    float c[4] = {0.f, 0.f, 0.f, 0.f};
    mma_bf16(c, a, b);

#pragma unroll
    for (int t = 0; t < 4; t++) {
        int r  = qr + ((t >= 2) ? 8 : 0);
        int cc = kp + (t & 1);
        float ref = 0.f;
        for (int k = 0; k < 16; k++)
            ref += __bfloat162float(pA[r*16 + k]) * __bfloat162float(pB[cc*16 + k]);
        if (fabsf(c[t] - ref) > 1e-2f) g_bad = 1;
    }
}

// ---------------------------------------------------------------------------
// Kernel 0: fp32 -> bf16 hi/lo split (guarded)
// ---------------------------------------------------------------------------
__global__ __launch_bounds__(256) void split_kernel(const float* __restrict__ src,
                                                    __nv_bfloat16* __restrict__ h,
                                                    __nv_bfloat16* __restrict__ l,
                                                    int n4) {
    if (g_bad) return;
    int i = blockIdx.x * blockDim.x + threadIdx.x;
    if (i >= n4) return;
    float4 v = ((const float4*)src)[i];
    __nv_bfloat16 h0 = __float2bfloat16_rn(v.x);
    __nv_bfloat16 h1 = __float2bfloat16_rn(v.y);
    __nv_bfloat16 h2 = __float2bfloat16_rn(v.z);
    __nv_bfloat16 h3 = __float2bfloat16_rn(v.w);
    __nv_bfloat16 l0 = __float2bfloat16_rn(v.x - __bfloat162float(h0));
    __nv_bfloat16 l1 = __float2bfloat16_rn(v.y - __bfloat162float(h1));
    __nv_bfloat16 l2 = __float2bfloat16_rn(v.z - __bfloat162float(h2));
    __nv_bfloat16 l3 = __float2bfloat16_rn(v.w - __bfloat162float(h3));
    ((__nv_bfloat162*)h)[2*i+0] = __halves2bfloat162(h0, h1);
    ((__nv_bfloat162*)h)[2*i+1] = __halves2bfloat162(h2, h3);
    ((__nv_bfloat162*)l)[2*i+0] = __halves2bfloat162(l0, l1);
    ((__nv_bfloat162*)l)[2*i+1] = __halves2bfloat162(l2, l3);
}

// ---------------------------------------------------------------------------
// Kernel 1: bf16x3 QKV GEMM via mma.sync (guarded on probe success).
// ---------------------------------------------------------------------------
#define RS   40
#define ARR  (128*RS)
#define STG  (4*ARR)
#define GEMM_SMEM (STG*2)        // 40960 bytes

__global__ __launch_bounds__(256) void qkv_mma(const float* __restrict__ bias) {
    if (g_bad) return;
    extern __shared__ __nv_bfloat16 sh[];

    int tid = threadIdx.x;
    int wid = tid >> 5, lid = tid & 31;
    int bn = blockIdx.x * 128, bm = blockIdx.y * 128;
    int wm = wid & 1, wn = wid >> 1;
    int qr = lid >> 2;
    int kp = (lid & 3) * 2;

    const __nv_bfloat16* bases[4] = {
        g_ah + (size_t)bm * KA_, g_al + (size_t)bm * KA_,
        g_wh + (size_t)bn * KA_, g_wl + (size_t)bn * KA_ };

    int ldr = tid >> 2, ldc = tid & 3;

    float4 stg[8];
    auto gload = [&](int k0) {
#pragma unroll
        for (int arr = 0; arr < 4; arr++)
#pragma unroll
            for (int t = 0; t < 2; t++) {
                int r = ldr + t * 64;
                stg[arr*2 + t] = *(const float4*)(bases[arr] + (size_t)r * KA_ + k0 + ldc * 8);
            }
    };
    auto swrite = [&]() {
#pragma unroll
        for (int arr = 0; arr < 4; arr++)
#pragma unroll
            for (int t = 0; t < 2; t++) {
                int r = ldr + t * 64;
                *(float4*)(sh + arr*ARR + r*RS + ldc*8) = stg[arr*2 + t];
            }
    };

    float acc[4][4][4];
#pragma unroll
    for (int i = 0; i < 4; i++)
#pragma unroll
        for (int j = 0; j < 4; j++)
#pragma unroll
            for (int k = 0; k < 4; k++) acc[i][j][k] = 0.f;

    gload(0);

    const int NITER = KA_ / 32;
    for (int it = 0; it < NITER; it++) {
        __syncthreads();
        swrite();
        __syncthreads();
        if (it + 1 < NITER) gload((it + 1) * 32);

        const __nv_bfloat16* sAh = sh;
        const __nv_bfloat16* sAl = sh + ARR;
        const __nv_bfloat16* sWh = sh + 2*ARR;
        const __nv_bfloat16* sWl = sh + 3*ARR;

#pragma unroll
        for (int ks = 0; ks < 2; ks++) {
            int kb = ks * 16 + kp;
            uint32_t aHf[4][4], aLf[4][4], bHf[4][2], bLf[4][2];
#pragma unroll
            for (int am = 0; am < 4; am++) {
                int o = (wm*64 + am*16 + qr) * RS + kb;
                aHf[am][0] = *(const uint32_t*)(sAh + o);
                aHf[am][1] = *(const uint32_t*)(sAh + o + 8*RS);
                aHf[am][2] = *(const uint32_t*)(sAh + o + 8);
                aHf[am][3] = *(const uint32_t*)(sAh + o + 8*RS + 8);
                aLf[am][0] = *(const uint32_t*)(sAl + o);
                aLf[am][1] = *(const uint32_t*)(sAl + o + 8*RS);
                aLf[am][2] = *(const uint32_t*)(sAl + o + 8);
                aLf[am][3] = *(const uint32_t*)(sAl + o + 8*RS + 8);
            }
#pragma unroll
            for (int nb = 0; nb < 4; nb++) {
                int o = (wn*32 + nb*8 + qr) * RS + kb;
                bHf[nb][0] = *(const uint32_t*)(sWh + o);
                bHf[nb][1] = *(const uint32_t*)(sWh + o + 8);
                bLf[nb][0] = *(const uint32_t*)(sWl + o);
                bLf[nb][1] = *(const uint32_t*)(sWl + o + 8);
            }
#pragma unroll
            for (int am = 0; am < 4; am++)
#pragma unroll
                for (int nb = 0; nb < 4; nb++) {
                    mma_bf16(acc[am][nb], aHf[am], bHf[nb]);
                    mma_bf16(acc[am][nb], aHf[am], bLf[nb]);
                    mma_bf16(acc[am][nb], aLf[am], bHf[nb]);
                }
        }
    }

    int b = bm >> 10;
#pragma unroll
    for (int am = 0; am < 4; am++) {
        int s0 = (bm & 1023) + wm * 64 + am * 16 + qr;
#pragma unroll
        for (int nb = 0; nb < 4; nb++) {
            int n0    = bn + wn * 32 + nb * 8;
            int h     = n0 / 384;
            int inner = n0 - h * 384;
            int part  = inner >> 7;
            int dd    = (inner & 127) + kp;
            float* dst = (part == 0) ? g_q : (part == 1) ? g_k : g_v;
            float b0v = bias[n0 + kp], b1v = bias[n0 + kp + 1];
            size_t rb = ((size_t)(b * H_ + h) * S_);
            float2 v0 = { acc[am][nb][0] + b0v, acc[am][nb][1] + b1v };
            *(float2*)&dst[(rb + s0) * HD_ + dd] = v0;
            float2 v1 = { acc[am][nb][2] + b0v, acc[am][nb][3] + b1v };
            *(float2*)&dst[(rb + s0 + 8) * HD_ + dd] = v1;
        }
    }
}

// ---------------------------------------------------------------------------
// Spot check: 64 sampled output elements vs direct fp32 dot products.
// ---------------------------------------------------------------------------
__global__ void spot_check(const float* __restrict__ hidden,
                           const float* __restrict__ w,
                           const float* __restrict__ bias) {
    if (g_bad) return;
    int m = blockIdx.x * 64 + 17;   // 64 blocks: m <= 4049 < 4096
    int n = blockIdx.x * 96 + 5;    //            n <= 6053 < 6144
    float ref = bias[n];
#pragma unroll 8
    for (int k = 0; k < KA_; k++)
        ref += hidden[(size_t)m*KA_ + k] * w[(size_t)n*KA_ + k];
    int b = m >> 10, s = m & 1023;
    int h = n / 384, inner = n - h * 384, part = inner >> 7, dd = inner & 127;
    const float* src = (part == 0) ? g_q : (part == 1) ? g_k : g_v;
    float got = src[((size_t)(b*H_ + h)*S_ + s)*HD_ + dd];
    if (fabsf(got - ref) > 0.03f + 0.02f * fabsf(ref)) g_bad = 1;
}

// ---------------------------------------------------------------------------
// Repair path: R1's known-good fp32 GEMM (runs only if g_bad).
// ---------------------------------------------------------------------------
__global__ __launch_bounds__(256) void qkv_fp32(const float* __restrict__ A,
                                                const float* __restrict__ W,
                                                const float* __restrict__ bias) {
    if (!g_bad) return;
    __shared__ float As[8][128];
    __shared__ float Bs[8][128];
    int tid = threadIdx.x;
    int bm = blockIdx.y * 128, bn = blockIdx.x * 128;
    int lr = tid >> 1;
    int lk = (tid & 1) * 4;
    const float* Ap = A + (size_t)(bm + lr) * D_ + lk;
    const float* Wp = W + (size_t)(bn + lr) * D_ + lk;
    int tx = tid & 15, ty = tid >> 4;

    float acc[8][8];
#pragma unroll
    for (int i = 0; i < 8; i++)
#pragma unroll
        for (int j = 0; j < 8; j++) acc[i][j] = 0.f;

    for (int k0 = 0; k0 < D_; k0 += 8) {
        float4 a4 = *(const float4*)(Ap + k0);
        float4 b4 = *(const float4*)(Wp + k0);
        __syncthreads();
        As[lk+0][lr] = a4.x; As[lk+1][lr] = a4.y; As[lk+2][lr] = a4.z; As[lk+3][lr] = a4.w;
        Bs[lk+0][lr] = b4.x; Bs[lk+1][lr] = b4.y; Bs[lk+2][lr] = b4.z; Bs[lk+3][lr] = b4.w;
        __syncthreads();
#pragma unroll
        for (int kk = 0; kk < 8; kk++) {
            float4 a0 = *(const float4*)&As[kk][ty*4];
            float4 a1 = *(const float4*)&As[kk][ty*4 + 64];
            float4 b0 = *(const float4*)&Bs[kk][tx*4];
            float4 b1 = *(const float4*)&Bs[kk][tx*4 + 64];
            float ra[8] = {a0.x,a0.y,a0.z,a0.w,a1.x,a1.y,a1.z,a1.w};
            float rb[8] = {b0.x,b0.y,b0.z,b0.w,b1.x,b1.y,b1.z,b1.w};
#pragma unroll
            for (int i = 0; i < 8; i++)
#pragma unroll
                for (int j = 0; j < 8; j++)
                    acc[i][j] += ra[i] * rb[j];
        }
    }

#pragma unroll
    for (int i = 0; i < 8; i++) {
        int m = bm + ((i < 4) ? ty*4 + i : 64 + ty*4 + (i - 4));
        int b = m >> 10, s = m & 1023;
#pragma unroll
        for (int j = 0; j < 8; j++) {
            int n = bn + ((j < 4) ? tx*4 + j : 64 + tx*4 + (j - 4));
            float v = acc[i][j] + bias[n];
            int h = n / 384;
            int inner = n - h * 384;
            int part = inner >> 7;
            int dd = inner & 127;
            float* dst = (part == 0) ? g_q : (part == 1) ? g_k : g_v;
            dst[((size_t)((b*H_ + h)*S_ + s)) * HD_ + dd] = v;
        }
    }
}

// ---------------------------------------------------------------------------
// Kernel 2: RoPE in-place on q or k.
// ---------------------------------------------------------------------------
__global__ __launch_bounds__(256) void rope_kernel(int which) {
    float* x = which ? g_k : g_q;
    int i = blockIdx.x * blockDim.x + threadIdx.x;
    const int total = B_ * H_ * S_ * 64;
    if (i >= total) return;
    int j = i & 63;
    int bhs = i >> 6;
    int s = bhs & (S_ - 1);
    float ang = (float)s * exp2f(-(float)j * (13.287712379549449f / 64.f));
    float sn, c;
    sincosf(ang, &sn, &c);
    float* p = x + (size_t)bhs * HD_ + j;
    float x1 = p[0], x2 = p[64];
    p[0]  = x1 * c - x2 * sn;
    p[64] = x2 * c + x1 * sn;
}

// ---------------------------------------------------------------------------
// Kernel 3: causal flash attention, fp32 (known-good).
// ---------------------------------------------------------------------------
#define ATTN_SMEM_FLOATS (64*129*2 + 64*128 + 64*65 + 64*3)
#define ATTN_SMEM_BYTES  (ATTN_SMEM_FLOATS * 4)

__global__ __launch_bounds__(256) void attn_kernel(float* __restrict__ out) {
    extern __shared__ float sm[];
    float* Qs   = sm;
    float* Ks   = Qs + 64*129;
    float* Vs   = Ks + 64*129;
    float* Sc   = Vs + 64*128;
    float* rowm = Sc + 64*65;
    float* rowl = rowm + 64;
    float* corr = rowl + 64;

    int tid = threadIdx.x;
    int qt = blockIdx.x, bh = blockIdx.y;
    int q0 = qt * 64;
    const float* Qb = g_q + (size_t)bh * S_ * HD_;
    const float* Kb = g_k + (size_t)bh * S_ * HD_;
    const float* Vb = g_v + (size_t)bh * S_ * HD_;

    const float scale = 0.08838834764831845f;
    {
        int c = tid & 127, r0 = tid >> 7;
#pragma unroll
        for (int it = 0; it < 32; it++) {
            int r = r0 + it * 2;
            Qs[r*129 + c] = Qb[(size_t)(q0 + r)*HD_ + c] * scale;
        }
    }
    if (tid < 64) { rowm[tid] = -1e30f; rowl[tid] = 0.f; }

    float o[32];
#pragma unroll
    for (int i = 0; i < 32; i++) o[i] = 0.f;

    int m = tid & 63, g = tid >> 6;
    int tx = tid & 15, ty = tid >> 4;

    for (int kt = 0; kt <= qt; kt++) {
        int k0 = kt * 64;
        __syncthreads();
        {
            int c = tid & 127, r0 = tid >> 7;
#pragma unroll
            for (int it = 0; it < 32; it++) {
                int r = r0 + it * 2;
                Ks[r*129 + c] = Kb[(size_t)(k0 + r)*HD_ + c];
                Vs[r*128 + c] = Vb[(size_t)(k0 + r)*HD_ + c];
            }
        }
        __syncthreads();

        float acc[4][4];
#pragma unroll
        for (int i = 0; i < 4; i++)
#pragma unroll
            for (int j = 0; j < 4; j++) acc[i][j] = 0.f;

#pragma unroll 4
        for (int kk = 0; kk < 128; kk++) {
            float a_[4], b_[4];
#pragma unroll
            for (int i = 0; i < 4; i++) a_[i] = Qs[(ty*4 + i)*129 + kk];
#pragma unroll
            for (int j = 0; j < 4; j++) b_[j] = Ks[(tx*4 + j)*129 + kk];
#pragma unroll
            for (int i = 0; i < 4; i++)
#pragma unroll
                for (int j = 0; j < 4; j++)
                    acc[i][j] += a_[i] * b_[j];
        }

        bool diag = (kt == qt);
#pragma unroll
        for (int i = 0; i < 4; i++) {
            int r = ty*4 + i;
#pragma unroll
            for (int j = 0; j < 4; j++) {
                int c = tx*4 + j;
                float v = acc[i][j];
                if (diag && c > r) v = -1e30f;
                Sc[r*65 + c] = v;
            }
        }
        __syncthreads();

        if (tid < 64) {
            int r = tid;
            float mo = rowm[r], mx = mo;
#pragma unroll 8
            for (int c = 0; c < 64; c++) mx = fmaxf(mx, Sc[r*65 + c]);
            float co = __expf(mo - mx);
            float su = 0.f;
#pragma unroll 8
            for (int c = 0; c < 64; c++) {
                float p = __expf(Sc[r*65 + c] - mx);
                Sc[r*65 + c] = p;
                su += p;
            }
            rowl[r] = rowl[r] * co + su;
            rowm[r] = mx;
            corr[r] = co;
        }
        __syncthreads();

        float co = corr[m];
#pragma unroll
        for (int i = 0; i < 32; i++) o[i] *= co;
#pragma unroll 4
        for (int n = 0; n < 64; n++) {
            float p = Sc[m*65 + n];
            const float4* vr = (const float4*)(Vs + n*128 + g*32);
#pragma unroll
            for (int i = 0; i < 8; i++) {
                float4 v4 = vr[i];
                o[i*4 + 0] += p * v4.x;
                o[i*4 + 1] += p * v4.y;
                o[i*4 + 2] += p * v4.z;
                o[i*4 + 3] += p * v4.w;
            }
        }
    }

    float invl = 1.f / rowl[m];
    int b = bh >> 4, h = bh & 15;
    int s = q0 + m;
    float* op = out + ((size_t)(b*S_ + s)) * D_ + h*HD_ + g*32;
#pragma unroll
    for (int i = 0; i < 32; i++) op[i] = o[i] * invl;
}

// ---------------------------------------------------------------------------
extern "C" void kernel_launch(void* const* d_in, const int* in_sizes, int n_in,
                              void* d_out, int out_size) {
    const float* hidden = (const float*)d_in[0];
    const float* w_qkv  = (const float*)d_in[1];
    const float* b_qkv  = (const float*)d_in[2];
    float* out = (float*)d_out;

    cudaFuncSetAttribute(attn_kernel, cudaFuncAttributeMaxDynamicSharedMemorySize,
                         ATTN_SMEM_BYTES);

    reset_flag<<<1, 1>>>();
    probe_mma<<<1, 32>>>();

    // fast path (skipped if probe failed)
    {
        int n4a = MA_ * KA_ / 4;
        split_kernel<<<(n4a + 255) / 256, 256>>>(hidden, g_ah, g_al, n4a);
        int n4w = NA_ * KA_ / 4;
        split_kernel<<<(n4w + 255) / 256, 256>>>(w_qkv, g_wh, g_wl, n4w);
        dim3 gg(NA_ / 128, MA_ / 128);
        qkv_mma<<<gg, 256, GEMM_SMEM>>>(b_qkv);
    }

    spot_check<<<64, 1>>>(hidden, w_qkv, b_qkv);

    // repair path (runs only if g_bad)
    qkv_fp32<<<dim3(NA_ / 128, MA_ / 128), 256>>>(hidden, w_qkv, b_qkv);

    // RoPE
    int total = B_ * H_ * S_ * 64;
    int nb = (total + 255) / 256;
    rope_kernel<<<nb, 256>>>(0);
    rope_kernel<<<nb, 256>>>(1);

    // attention
    attn_kernel<<<dim3(S_ / 64, B_ * H_), 256, ATTN_SMEM_BYTES>>>(out);
}

// round 11
// speedup vs baseline: 1.8900x; 1.8900x over previous
#include <cuda_runtime.h>
#include <cuda_bf16.h>
#include <cstdint>

#define B_  4
#define S_  1024
#define D_  2048
#define H_  16
#define HD_ 128

#define MA_ (B_*S_)    // 4096
#define NA_ (3*D_)     // 6144
#define KA_ D_         // 2048

#define TX_ 48         // n tiles
#define TY_ 32         // m tiles

// Scratch (allocation-free rule)
__device__ float g_q[B_*H_*S_*HD_];
__device__ float g_k[B_*H_*S_*HD_];
__device__ float g_v[B_*H_*S_*HD_];
__device__ __align__(16) __nv_bfloat16 g_ah[(size_t)MA_*KA_];
__device__ __align__(16) __nv_bfloat16 g_al[(size_t)MA_*KA_];
__device__ __align__(16) __nv_bfloat16 g_wh[(size_t)NA_*KA_];
__device__ __align__(16) __nv_bfloat16 g_wl[(size_t)NA_*KA_];
__device__ int g_kill;
__device__ int g_tilebad[TY_*TX_];

__device__ __forceinline__ void mma_bf16(float c[4], const uint32_t a[4],
                                         const uint32_t b[2]) {
    asm volatile("mma.sync.aligned.m16n8k16.row.col.f32.bf16.bf16.f32 "
        "{%0,%1,%2,%3}, {%4,%5,%6,%7}, {%8,%9}, {%0,%1,%2,%3};"
        : "+f"(c[0]), "+f"(c[1]), "+f"(c[2]), "+f"(c[3])
        : "r"(a[0]), "r"(a[1]), "r"(a[2]), "r"(a[3]), "r"(b[0]), "r"(b[1]));
}

__device__ __forceinline__ void split4(float4 v, __nv_bfloat16* hp,
                                       __nv_bfloat16* lp, int off) {
    __nv_bfloat16 h0 = __float2bfloat16_rn(v.x);
    __nv_bfloat16 h1 = __float2bfloat16_rn(v.y);
    __nv_bfloat16 h2 = __float2bfloat16_rn(v.z);
    __nv_bfloat16 h3 = __float2bfloat16_rn(v.w);
    __nv_bfloat16 l0 = __float2bfloat16_rn(v.x - __bfloat162float(h0));
    __nv_bfloat16 l1 = __float2bfloat16_rn(v.y - __bfloat162float(h1));
    __nv_bfloat16 l2 = __float2bfloat16_rn(v.z - __bfloat162float(h2));
    __nv_bfloat16 l3 = __float2bfloat16_rn(v.w - __bfloat162float(h3));
    ((__nv_bfloat162*)hp)[2*off+0] = __halves2bfloat162(h0, h1);
    ((__nv_bfloat162*)hp)[2*off+1] = __halves2bfloat162(h2, h3);
    ((__nv_bfloat162*)lp)[2*off+0] = __halves2bfloat162(l0, l1);
    ((__nv_bfloat162*)lp)[2*off+1] = __halves2bfloat162(l2, l3);
}

// ---------------------------------------------------------------------------
__global__ void reset_flags() {
    int i = blockIdx.x * 256 + threadIdx.x;
    if (i == 0) g_kill = 0;
    if (i < TY_*TX_) g_tilebad[i] = 0;
}

// mini split: A rows 0..127 (all k) and W rows 0..127 -> enough for tile (0,0)
__global__ __launch_bounds__(256) void mini_split(const float* __restrict__ hidden,
                                                  const float* __restrict__ w) {
    int i = blockIdx.x * 256 + threadIdx.x;    // 0..131071
    const float* src; __nv_bfloat16 *hp, *lp; int off;
    if (i < 65536) { src = hidden; hp = g_ah; lp = g_al; off = i; }
    else           { src = w;      hp = g_wh; lp = g_wl; off = i - 65536; }
    split4(((const float4*)src)[off], hp, lp, off);
}

// full split (skipped if mini test failed)
#define N4A (MA_*KA_/4)      // 2097152
#define N4T (N4A + NA_*KA_/4)// 5242880
__global__ __launch_bounds__(256) void split_all(const float* __restrict__ hidden,
                                                 const float* __restrict__ w) {
    if (g_kill) return;
    int i4 = blockIdx.x * 256 + threadIdx.x;   // 0..1310719
    int base = i4 * 4;
    const float* src; __nv_bfloat16 *hp, *lp; int off;
    if (base < N4A) { src = hidden; hp = g_ah; lp = g_al; off = base; }
    else            { src = w;      hp = g_wh; lp = g_wl; off = base - N4A; }
    float4 v[4];
#pragma unroll
    for (int t = 0; t < 4; t++) v[t] = ((const float4*)src)[off + t];
#pragma unroll
    for (int t = 0; t < 4; t++) split4(v[t], hp, lp, off + t);
}

// ---------------------------------------------------------------------------
// bf16x3 QKV GEMM via mma.sync.  Term-OUTER ordering: consecutive HMMAs are
// independent (distinct accumulators) -> no dependent HMMA chains.
// ---------------------------------------------------------------------------
#define RS   40
#define ARR  (128*RS)
#define STG  (4*ARR)
#define GEMM_SMEM (STG*2)        // 40960 bytes

__global__ __launch_bounds__(256) void qkv_mma(const float* __restrict__ bias) {
    if (g_kill) return;
    extern __shared__ __nv_bfloat16 sh[];

    int tid = threadIdx.x;
    int wid = tid >> 5, lid = tid & 31;
    int bn = blockIdx.x * 128, bm = blockIdx.y * 128;
    int wm = wid & 1, wn = wid >> 1;
    int qr = lid >> 2;
    int kp = (lid & 3) * 2;

    const __nv_bfloat16* baseA_h = g_ah + (size_t)bm * KA_;
    const __nv_bfloat16* baseA_l = g_al + (size_t)bm * KA_;
    const __nv_bfloat16* baseW_h = g_wh + (size_t)bn * KA_;
    const __nv_bfloat16* baseW_l = g_wl + (size_t)bn * KA_;

    int ldr = tid >> 2, ldc = tid & 3;

    float acc[4][4][4];
#pragma unroll
    for (int i = 0; i < 4; i++)
#pragma unroll
        for (int j = 0; j < 4; j++)
#pragma unroll
            for (int k = 0; k < 4; k++) acc[i][j][k] = 0.f;

    float4 stg[8];
#pragma unroll
    for (int t = 0; t < 2; t++) {
        int r = ldr + t * 64;
        size_t go = (size_t)r * KA_ + ldc * 8;
        stg[0*2+t] = *(const float4*)(baseA_h + go);
        stg[1*2+t] = *(const float4*)(baseA_l + go);
        stg[2*2+t] = *(const float4*)(baseW_h + go);
        stg[3*2+t] = *(const float4*)(baseW_l + go);
    }

    const int NITER = KA_ / 32;   // 64
    for (int it = 0; it < NITER; it++) {
        __syncthreads();
#pragma unroll
        for (int arr = 0; arr < 4; arr++)
#pragma unroll
            for (int t = 0; t < 2; t++) {
                int r = ldr + t * 64;
                *(float4*)(sh + arr*ARR + r*RS + ldc*8) = stg[arr*2 + t];
            }
        __syncthreads();
        if (it + 1 < NITER) {
            int k0 = (it + 1) * 32;
#pragma unroll
            for (int t = 0; t < 2; t++) {
                int r = ldr + t * 64;
                size_t go = (size_t)r * KA_ + k0 + ldc * 8;
                stg[0*2+t] = *(const float4*)(baseA_h + go);
                stg[1*2+t] = *(const float4*)(baseA_l + go);
                stg[2*2+t] = *(const float4*)(baseW_h + go);
                stg[3*2+t] = *(const float4*)(baseW_l + go);
            }
        }

        const __nv_bfloat16* sAh = sh;
        const __nv_bfloat16* sAl = sh + ARR;
        const __nv_bfloat16* sWh = sh + 2*ARR;
        const __nv_bfloat16* sWl = sh + 3*ARR;

#pragma unroll
        for (int ks = 0; ks < 2; ks++) {
            int kb = ks * 16 + kp;
            uint32_t aHf[4][4], aLf[4][4], bHf[4][2], bLf[4][2];
#pragma unroll
            for (int am = 0; am < 4; am++) {
                int o = (wm*64 + am*16 + qr) * RS + kb;
                aHf[am][0] = *(const uint32_t*)(sAh + o);
                aHf[am][1] = *(const uint32_t*)(sAh + o + 8*RS);
                aHf[am][2] = *(const uint32_t*)(sAh + o + 8);
                aHf[am][3] = *(const uint32_t*)(sAh + o + 8*RS + 8);
                aLf[am][0] = *(const uint32_t*)(sAl + o);
                aLf[am][1] = *(const uint32_t*)(sAl + o + 8*RS);
                aLf[am][2] = *(const uint32_t*)(sAl + o + 8);
                aLf[am][3] = *(const uint32_t*)(sAl + o + 8*RS + 8);
            }
#pragma unroll
            for (int nb = 0; nb < 4; nb++) {
                int o = (wn*32 + nb*8 + qr) * RS + kb;
                bHf[nb][0] = *(const uint32_t*)(sWh + o);
                bHf[nb][1] = *(const uint32_t*)(sWh + o + 8);
                bLf[nb][0] = *(const uint32_t*)(sWl + o);
                bLf[nb][1] = *(const uint32_t*)(sWl + o + 8);
            }
            // term-outer: consecutive mmas touch different accumulators
#pragma unroll
            for (int am = 0; am < 4; am++)
#pragma unroll
                for (int nb = 0; nb < 4; nb++)
                    mma_bf16(acc[am][nb], aHf[am], bHf[nb]);
#pragma unroll
            for (int am = 0; am < 4; am++)
#pragma unroll
                for (int nb = 0; nb < 4; nb++)
                    mma_bf16(acc[am][nb], aHf[am], bLf[nb]);
#pragma unroll
            for (int am = 0; am < 4; am++)
#pragma unroll
                for (int nb = 0; nb < 4; nb++)
                    mma_bf16(acc[am][nb], aLf[am], bHf[nb]);
        }
    }

    int b = bm >> 10;
#pragma unroll
    for (int am = 0; am < 4; am++) {
        int s0 = (bm & 1023) + wm * 64 + am * 16 + qr;
#pragma unroll
        for (int nb = 0; nb < 4; nb++) {
            int n0    = bn + wn * 32 + nb * 8;
            int h     = n0 / 384;
            int inner = n0 - h * 384;
            int part  = inner >> 7;
            int dd    = (inner & 127) + kp;
            float* dst = (part == 0) ? g_q : (part == 1) ? g_k : g_v;
            float b0v = bias[n0 + kp], b1v = bias[n0 + kp + 1];
            size_t rb = ((size_t)(b * H_ + h) * S_);
            float2 v0 = { acc[am][nb][0] + b0v, acc[am][nb][1] + b1v };
            *(float2*)&dst[(rb + s0) * HD_ + dd] = v0;
            float2 v1 = { acc[am][nb][2] + b0v, acc[am][nb][3] + b1v };
            *(float2*)&dst[(rb + s0 + 8) * HD_ + dd] = v1;
        }
    }
}

// ---------------------------------------------------------------------------
// Verification: 32 fp32-dot samples per 128x128 tile.
// ---------------------------------------------------------------------------
__device__ __forceinline__ void check_sample(int m, int n,
                                             const float* hidden, const float* w,
                                             const float* bias, int* flag) {
    float ref = bias[n];
    const float* hr = hidden + (size_t)m * KA_;
    const float* wr = w + (size_t)n * KA_;
#pragma unroll 8
    for (int k = 0; k < KA_; k++) ref += hr[k] * wr[k];
    int b = m >> 10, s = m & 1023;
    int h = n / 384, inner = n - h * 384, part = inner >> 7, dd = inner & 127;
    const float* src = (part == 0) ? g_q : (part == 1) ? g_k : g_v;
    float got = src[((size_t)(b*H_ + h)*S_ + s)*HD_ + dd];
    if (!(fabsf(got - ref) <= 0.02f + 0.01f*fabsf(ref))) *flag = 1;  // catches NaN
}

__global__ void mini_verify(const float* __restrict__ hidden,
                            const float* __restrict__ w,
                            const float* __restrict__ bias) {
    int t = threadIdx.x;
    check_sample((t*37 + 11) & 127, (t*53 + 7) & 127, hidden, w, bias, &g_kill);
}

__global__ void verify_tiles(const float* __restrict__ hidden,
                             const float* __restrict__ w,
                             const float* __restrict__ bias) {
    if (g_kill) return;
    int t = threadIdx.x;
    int m = blockIdx.y * 128 + ((t*37 + 11) & 127);
    int n = blockIdx.x * 128 + ((t*53 + 7) & 127);
    check_sample(m, n, hidden, w, bias, &g_tilebad[blockIdx.y*TX_ + blockIdx.x]);
}

// ---------------------------------------------------------------------------
// Repair: known-good fp32 GEMM per flagged tile.
// ---------------------------------------------------------------------------
__global__ __launch_bounds__(256) void qkv_fp32(const float* __restrict__ A,
                                                const float* __restrict__ W,
                                                const float* __restrict__ bias) {
    if (!(g_kill || g_tilebad[blockIdx.y*TX_ + blockIdx.x])) return;
    __shared__ float As[8][128];
    __shared__ float Bs[8][128];
    int tid = threadIdx.x;
    int bm = blockIdx.y * 128, bn = blockIdx.x * 128;
    int lr = tid >> 1;
    int lk = (tid & 1) * 4;
    const float* Ap = A + (size_t)(bm + lr) * D_ + lk;
    const float* Wp = W + (size_t)(bn + lr) * D_ + lk;
    int tx = tid & 15, ty = tid >> 4;

    float acc[8][8];
#pragma unroll
    for (int i = 0; i < 8; i++)
#pragma unroll
        for (int j = 0; j < 8; j++) acc[i][j] = 0.f;

    for (int k0 = 0; k0 < D_; k0 += 8) {
        float4 a4 = *(const float4*)(Ap + k0);
        float4 b4 = *(const float4*)(Wp + k0);
        __syncthreads();
        As[lk+0][lr] = a4.x; As[lk+1][lr] = a4.y; As[lk+2][lr] = a4.z; As[lk+3][lr] = a4.w;
        Bs[lk+0][lr] = b4.x; Bs[lk+1][lr] = b4.y; Bs[lk+2][lr] = b4.z; Bs[lk+3][lr] = b4.w;
        __syncthreads();
#pragma unroll
        for (int kk = 0; kk < 8; kk++) {
            float4 a0 = *(const float4*)&As[kk][ty*4];
            float4 a1 = *(const float4*)&As[kk][ty*4 + 64];
            float4 b0 = *(const float4*)&Bs[kk][tx*4];
            float4 b1 = *(const float4*)&Bs[kk][tx*4 + 64];
            float ra[8] = {a0.x,a0.y,a0.z,a0.w,a1.x,a1.y,a1.z,a1.w};
            float rb[8] = {b0.x,b0.y,b0.z,b0.w,b1.x,b1.y,b1.z,b1.w};
#pragma unroll
            for (int i = 0; i < 8; i++)
#pragma unroll
                for (int j = 0; j < 8; j++)
                    acc[i][j] += ra[i] * rb[j];
        }
    }

#pragma unroll
    for (int i = 0; i < 8; i++) {
        int m = bm + ((i < 4) ? ty*4 + i : 64 + ty*4 + (i - 4));
        int b = m >> 10, s = m & 1023;
#pragma unroll
        for (int j = 0; j < 8; j++) {
            int n = bn + ((j < 4) ? tx*4 + j : 64 + tx*4 + (j - 4));
            float v = acc[i][j] + bias[n];
            int h = n / 384;
            int inner = n - h * 384;
            int part = inner >> 7;
            int dd = inner & 127;
            float* dst = (part == 0) ? g_q : (part == 1) ? g_k : g_v;
            dst[((size_t)((b*H_ + h)*S_ + s)) * HD_ + dd] = v;
        }
    }
}

// ---------------------------------------------------------------------------
// RoPE in-place on q or k.
// ---------------------------------------------------------------------------
__global__ __launch_bounds__(256) void rope_kernel(int which) {
    float* x = which ? g_k : g_q;
    int i = blockIdx.x * blockDim.x + threadIdx.x;
    const int total = B_ * H_ * S_ * 64;
    if (i >= total) return;
    int j = i & 63;
    int bhs = i >> 6;
    int s = bhs & (S_ - 1);
    float ang = (float)s * exp2f(-(float)j * (13.287712379549449f / 64.f));
    float sn, c;
    sincosf(ang, &sn, &c);
    float* p = x + (size_t)bhs * HD_ + j;
    float x1 = p[0], x2 = p[64];
    p[0]  = x1 * c - x2 * sn;
    p[64] = x2 * c + x1 * sn;
}

// ---------------------------------------------------------------------------
// Causal flash attention, fp32 (known-good).
// ---------------------------------------------------------------------------
#define ATTN_SMEM_FLOATS (64*129*2 + 64*128 + 64*65 + 64*3)
#define ATTN_SMEM_BYTES  (ATTN_SMEM_FLOATS * 4)

__global__ __launch_bounds__(256) void attn_kernel(float* __restrict__ out) {
    extern __shared__ float sm[];
    float* Qs   = sm;
    float* Ks   = Qs + 64*129;
    float* Vs   = Ks + 64*129;
    float* Sc   = Vs + 64*128;
    float* rowm = Sc + 64*65;
    float* rowl = rowm + 64;
    float* corr = rowl + 64;

    int tid = threadIdx.x;
    int qt = blockIdx.x, bh = blockIdx.y;
    int q0 = qt * 64;
    const float* Qb = g_q + (size_t)bh * S_ * HD_;
    const float* Kb = g_k + (size_t)bh * S_ * HD_;
    const float* Vb = g_v + (size_t)bh * S_ * HD_;

    const float scale = 0.08838834764831845f;
    {
        int c = tid & 127, r0 = tid >> 7;
#pragma unroll
        for (int it = 0; it < 32; it++) {
            int r = r0 + it * 2;
            Qs[r*129 + c] = Qb[(size_t)(q0 + r)*HD_ + c] * scale;
        }
    }
    if (tid < 64) { rowm[tid] = -1e30f; rowl[tid] = 0.f; }

    float o[32];
#pragma unroll
    for (int i = 0; i < 32; i++) o[i] = 0.f;

    int m = tid & 63, g = tid >> 6;
    int tx = tid & 15, ty = tid >> 4;

    for (int kt = 0; kt <= qt; kt++) {
        int k0 = kt * 64;
        __syncthreads();
        {
            int c = tid & 127, r0 = tid >> 7;
#pragma unroll
            for (int it = 0; it < 32; it++) {
                int r = r0 + it * 2;
                Ks[r*129 + c] = Kb[(size_t)(k0 + r)*HD_ + c];
                Vs[r*128 + c] = Vb[(size_t)(k0 + r)*HD_ + c];
            }
        }
        __syncthreads();

        float acc[4][4];
#pragma unroll
        for (int i = 0; i < 4; i++)
#pragma unroll
            for (int j = 0; j < 4; j++) acc[i][j] = 0.f;

#pragma unroll 4
        for (int kk = 0; kk < 128; kk++) {
            float a_[4], b_[4];
#pragma unroll
            for (int i = 0; i < 4; i++) a_[i] = Qs[(ty*4 + i)*129 + kk];
#pragma unroll
            for (int j = 0; j < 4; j++) b_[j] = Ks[(tx*4 + j)*129 + kk];
#pragma unroll
            for (int i = 0; i < 4; i++)
#pragma unroll
                for (int j = 0; j < 4; j++)
                    acc[i][j] += a_[i] * b_[j];
        }

        bool diag = (kt == qt);
#pragma unroll
        for (int i = 0; i < 4; i++) {
            int r = ty*4 + i;
#pragma unroll
            for (int j = 0; j < 4; j++) {
                int c = tx*4 + j;
                float v = acc[i][j];
                if (diag && c > r) v = -1e30f;
                Sc[r*65 + c] = v;
            }
        }
        __syncthreads();

        if (tid < 64) {
            int r = tid;
            float mo = rowm[r], mx = mo;
#pragma unroll 8
            for (int c = 0; c < 64; c++) mx = fmaxf(mx, Sc[r*65 + c]);
            float co = __expf(mo - mx);
            float su = 0.f;
#pragma unroll 8
            for (int c = 0; c < 64; c++) {
                float p = __expf(Sc[r*65 + c] - mx);
                Sc[r*65 + c] = p;
                su += p;
            }
            rowl[r] = rowl[r] * co + su;
            rowm[r] = mx;
            corr[r] = co;
        }
        __syncthreads();

        float co = corr[m];
#pragma unroll
        for (int i = 0; i < 32; i++) o[i] *= co;
#pragma unroll 4
        for (int n = 0; n < 64; n++) {
            float p = Sc[m*65 + n];
            const float4* vr = (const float4*)(Vs + n*128 + g*32);
#pragma unroll
            for (int i = 0; i < 8; i++) {
                float4 v4 = vr[i];
                o[i*4 + 0] += p * v4.x;
                o[i*4 + 1] += p * v4.y;
                o[i*4 + 2] += p * v4.z;
                o[i*4 + 3] += p * v4.w;
            }
        }
    }

    float invl = 1.f / rowl[m];
    int b = bh >> 4, h = bh & 15;
    int s = q0 + m;
    float* op = out + ((size_t)(b*S_ + s)) * D_ + h*HD_ + g*32;
#pragma unroll
    for (int i = 0; i < 32; i++) op[i] = o[i] * invl;
}

// ---------------------------------------------------------------------------
extern "C" void kernel_launch(void* const* d_in, const int* in_sizes, int n_in,
                              void* d_out, int out_size) {
    const float* hidden = (const float*)d_in[0];
    const float* w_qkv  = (const float*)d_in[1];
    const float* b_qkv  = (const float*)d_in[2];
    float* out = (float*)d_out;

    cudaFuncSetAttribute(attn_kernel, cudaFuncAttributeMaxDynamicSharedMemorySize,
                         ATTN_SMEM_BYTES);

    reset_flags<<<6, 256>>>();

    // mini test: tile (0,0) end-to-end through the mma path
    mini_split<<<512, 256>>>(hidden, w_qkv);
    qkv_mma<<<dim3(1, 1), 256, GEMM_SMEM>>>(b_qkv);
    mini_verify<<<1, 32>>>(hidden, w_qkv, b_qkv);

    // full fast path (guarded by g_kill)
    split_all<<<5120, 256>>>(hidden, w_qkv);
    qkv_mma<<<dim3(TX_, TY_), 256, GEMM_SMEM>>>(b_qkv);
    verify_tiles<<<dim3(TX_, TY_), 32>>>(hidden, w_qkv, b_qkv);

    // per-tile repair (no-op where fast path verified)
    qkv_fp32<<<dim3(TX_, TY_), 256>>>(hidden, w_qkv, b_qkv);

    // RoPE
    int total = B_ * H_ * S_ * 64;
    int nb = (total + 255) / 256;
    rope_kernel<<<nb, 256>>>(0);
    rope_kernel<<<nb, 256>>>(1);

    // attention
    attn_kernel<<<dim3(S_ / 64, B_ * H_), 256, ATTN_SMEM_BYTES>>>(out);
}

// round 12
// speedup vs baseline: 2.2643x; 1.1981x over previous
#include <cuda_runtime.h>
#include <cuda_bf16.h>
#include <cstdint>

#define B_  4
#define S_  1024
#define D_  2048
#define H_  16
#define HD_ 128

#define MA_ (B_*S_)    // 4096
#define NA_ (3*D_)     // 6144
#define KA_ D_         // 2048

#define TX_ 48
#define TY_ 32

// Scratch (allocation-free rule)
__device__ float g_q[B_*H_*S_*HD_];
__device__ float g_k[B_*H_*S_*HD_];
__device__ float g_v[B_*H_*S_*HD_];
__device__ __align__(16) __nv_bfloat16 g_ah[(size_t)MA_*KA_];
__device__ __align__(16) __nv_bfloat16 g_al[(size_t)MA_*KA_];
__device__ __align__(16) __nv_bfloat16 g_wh[(size_t)NA_*KA_];
__device__ __align__(16) __nv_bfloat16 g_wl[(size_t)NA_*KA_];
// attention bf16 operands (q/k: [b,h,s,d]; v transposed: [b,h,d,s])
__device__ __align__(16) __nv_bfloat16 g_qh[B_*H_*S_*HD_];
__device__ __align__(16) __nv_bfloat16 g_ql[B_*H_*S_*HD_];
__device__ __align__(16) __nv_bfloat16 g_kh[B_*H_*S_*HD_];
__device__ __align__(16) __nv_bfloat16 g_kl[B_*H_*S_*HD_];
__device__ __align__(16) __nv_bfloat16 g_vth[B_*H_*S_*HD_];
__device__ __align__(16) __nv_bfloat16 g_vtl[B_*H_*S_*HD_];
__device__ int g_tilebad[TY_*TX_];

__device__ __forceinline__ void mma_bf16(float c[4], const uint32_t a[4],
                                         const uint32_t b[2]) {
    asm volatile("mma.sync.aligned.m16n8k16.row.col.f32.bf16.bf16.f32 "
        "{%0,%1,%2,%3}, {%4,%5,%6,%7}, {%8,%9}, {%0,%1,%2,%3};"
        : "+f"(c[0]), "+f"(c[1]), "+f"(c[2]), "+f"(c[3])
        : "r"(a[0]), "r"(a[1]), "r"(a[2]), "r"(a[3]), "r"(b[0]), "r"(b[1]));
}

__device__ __forceinline__ void split4(float4 v, __nv_bfloat16* hp,
                                       __nv_bfloat16* lp, int off) {
    __nv_bfloat16 h0 = __float2bfloat16_rn(v.x);
    __nv_bfloat16 h1 = __float2bfloat16_rn(v.y);
    __nv_bfloat16 h2 = __float2bfloat16_rn(v.z);
    __nv_bfloat16 h3 = __float2bfloat16_rn(v.w);
    __nv_bfloat16 l0 = __float2bfloat16_rn(v.x - __bfloat162float(h0));
    __nv_bfloat16 l1 = __float2bfloat16_rn(v.y - __bfloat162float(h1));
    __nv_bfloat16 l2 = __float2bfloat16_rn(v.z - __bfloat162float(h2));
    __nv_bfloat16 l3 = __float2bfloat16_rn(v.w - __bfloat162float(h3));
    ((__nv_bfloat162*)hp)[2*off+0] = __halves2bfloat162(h0, h1);
    ((__nv_bfloat162*)hp)[2*off+1] = __halves2bfloat162(h2, h3);
    ((__nv_bfloat162*)lp)[2*off+0] = __halves2bfloat162(l0, l1);
    ((__nv_bfloat162*)lp)[2*off+1] = __halves2bfloat162(l2, l3);
}

// ---------------------------------------------------------------------------
__global__ void reset_flags() {
    int i = blockIdx.x * 256 + threadIdx.x;
    if (i < TY_*TX_) g_tilebad[i] = 0;
}

#define N4A (MA_*KA_/4)
__global__ __launch_bounds__(256) void split_all(const float* __restrict__ hidden,
                                                 const float* __restrict__ w) {
    int i4 = blockIdx.x * 256 + threadIdx.x;
    int base = i4 * 4;
    const float* src; __nv_bfloat16 *hp, *lp; int off;
    if (base < N4A) { src = hidden; hp = g_ah; lp = g_al; off = base; }
    else            { src = w;      hp = g_wh; lp = g_wl; off = base - N4A; }
    float4 v[4];
#pragma unroll
    for (int t = 0; t < 4; t++) v[t] = ((const float4*)src)[off + t];
#pragma unroll
    for (int t = 0; t < 4; t++) split4(v[t], hp, lp, off + t);
}

// ---------------------------------------------------------------------------
// bf16x3 QKV GEMM via mma.sync (validated R11: term-outer ordering).
// ---------------------------------------------------------------------------
#define RS   40
#define ARR  (128*RS)
#define GEMM_SMEM (4*ARR*2)      // 40960 bytes

__global__ __launch_bounds__(256) void qkv_mma(const float* __restrict__ bias) {
    extern __shared__ __nv_bfloat16 sh[];

    int tid = threadIdx.x;
    int wid = tid >> 5, lid = tid & 31;
    int bn = blockIdx.x * 128, bm = blockIdx.y * 128;
    int wm = wid & 1, wn = wid >> 1;
    int qr = lid >> 2;
    int kp = (lid & 3) * 2;

    const __nv_bfloat16* baseA_h = g_ah + (size_t)bm * KA_;
    const __nv_bfloat16* baseA_l = g_al + (size_t)bm * KA_;
    const __nv_bfloat16* baseW_h = g_wh + (size_t)bn * KA_;
    const __nv_bfloat16* baseW_l = g_wl + (size_t)bn * KA_;

    int ldr = tid >> 2, ldc = tid & 3;

    float acc[4][4][4];
#pragma unroll
    for (int i = 0; i < 4; i++)
#pragma unroll
        for (int j = 0; j < 4; j++)
#pragma unroll
            for (int k = 0; k < 4; k++) acc[i][j][k] = 0.f;

    float4 stg[8];
#pragma unroll
    for (int t = 0; t < 2; t++) {
        int r = ldr + t * 64;
        size_t go = (size_t)r * KA_ + ldc * 8;
        stg[0*2+t] = *(const float4*)(baseA_h + go);
        stg[1*2+t] = *(const float4*)(baseA_l + go);
        stg[2*2+t] = *(const float4*)(baseW_h + go);
        stg[3*2+t] = *(const float4*)(baseW_l + go);
    }

    const int NITER = KA_ / 32;
    for (int it = 0; it < NITER; it++) {
        __syncthreads();
#pragma unroll
        for (int arr = 0; arr < 4; arr++)
#pragma unroll
            for (int t = 0; t < 2; t++) {
                int r = ldr + t * 64;
                *(float4*)(sh + arr*ARR + r*RS + ldc*8) = stg[arr*2 + t];
            }
        __syncthreads();
        if (it + 1 < NITER) {
            int k0 = (it + 1) * 32;
#pragma unroll
            for (int t = 0; t < 2; t++) {
                int r = ldr + t * 64;
                size_t go = (size_t)r * KA_ + k0 + ldc * 8;
                stg[0*2+t] = *(const float4*)(baseA_h + go);
                stg[1*2+t] = *(const float4*)(baseA_l + go);
                stg[2*2+t] = *(const float4*)(baseW_h + go);
                stg[3*2+t] = *(const float4*)(baseW_l + go);
            }
        }

        const __nv_bfloat16* sAh = sh;
        const __nv_bfloat16* sAl = sh + ARR;
        const __nv_bfloat16* sWh = sh + 2*ARR;
        const __nv_bfloat16* sWl = sh + 3*ARR;

#pragma unroll
        for (int ks = 0; ks < 2; ks++) {
            int kb = ks * 16 + kp;
            uint32_t aHf[4][4], aLf[4][4], bHf[4][2], bLf[4][2];
#pragma unroll
            for (int am = 0; am < 4; am++) {
                int o = (wm*64 + am*16 + qr) * RS + kb;
                aHf[am][0] = *(const uint32_t*)(sAh + o);
                aHf[am][1] = *(const uint32_t*)(sAh + o + 8*RS);
                aHf[am][2] = *(const uint32_t*)(sAh + o + 8);
                aHf[am][3] = *(const uint32_t*)(sAh + o + 8*RS + 8);
                aLf[am][0] = *(const uint32_t*)(sAl + o);
                aLf[am][1] = *(const uint32_t*)(sAl + o + 8*RS);
                aLf[am][2] = *(const uint32_t*)(sAl + o + 8);
                aLf[am][3] = *(const uint32_t*)(sAl + o + 8*RS + 8);
            }
#pragma unroll
            for (int nb = 0; nb < 4; nb++) {
                int o = (wn*32 + nb*8 + qr) * RS + kb;
                bHf[nb][0] = *(const uint32_t*)(sWh + o);
                bHf[nb][1] = *(const uint32_t*)(sWh + o + 8);
                bLf[nb][0] = *(const uint32_t*)(sWl + o);
                bLf[nb][1] = *(const uint32_t*)(sWl + o + 8);
            }
#pragma unroll
            for (int am = 0; am < 4; am++)
#pragma unroll
                for (int nb = 0; nb < 4; nb++)
                    mma_bf16(acc[am][nb], aHf[am], bHf[nb]);
#pragma unroll
            for (int am = 0; am < 4; am++)
#pragma unroll
                for (int nb = 0; nb < 4; nb++)
                    mma_bf16(acc[am][nb], aHf[am], bLf[nb]);
#pragma unroll
            for (int am = 0; am < 4; am++)
#pragma unroll
                for (int nb = 0; nb < 4; nb++)
                    mma_bf16(acc[am][nb], aLf[am], bHf[nb]);
        }
    }

    int b = bm >> 10;
#pragma unroll
    for (int am = 0; am < 4; am++) {
        int s0 = (bm & 1023) + wm * 64 + am * 16 + qr;
#pragma unroll
        for (int nb = 0; nb < 4; nb++) {
            int n0    = bn + wn * 32 + nb * 8;
            int h     = n0 / 384;
            int inner = n0 - h * 384;
            int part  = inner >> 7;
            int dd    = (inner & 127) + kp;
            float* dst = (part == 0) ? g_q : (part == 1) ? g_k : g_v;
            float b0v = bias[n0 + kp], b1v = bias[n0 + kp + 1];
            size_t rb = ((size_t)(b * H_ + h) * S_);
            float2 v0 = { acc[am][nb][0] + b0v, acc[am][nb][1] + b1v };
            *(float2*)&dst[(rb + s0) * HD_ + dd] = v0;
            float2 v1 = { acc[am][nb][2] + b0v, acc[am][nb][3] + b1v };
            *(float2*)&dst[(rb + s0 + 8) * HD_ + dd] = v1;
        }
    }
}

// ---------------------------------------------------------------------------
// Parallel per-tile verify: 32 samples/tile, 8 threads per sample.
// ---------------------------------------------------------------------------
__global__ __launch_bounds__(256) void verify_tiles(const float* __restrict__ hidden,
                                                    const float* __restrict__ w,
                                                    const float* __restrict__ bias) {
    int t = threadIdx.x;
    int sid = t >> 3, ln = t & 7;
    int m = blockIdx.y * 128 + ((sid*37 + 11) & 127);
    int n = blockIdx.x * 128 + ((sid*53 + 7) & 127);
    const float* hr = hidden + (size_t)m * KA_;
    const float* wr = w + (size_t)n * KA_;
    float p = 0.f;
    int k0 = ln * 256;
#pragma unroll 8
    for (int k = 0; k < 256; k++) p += hr[k0 + k] * wr[k0 + k];
#pragma unroll
    for (int off = 4; off > 0; off >>= 1)
        p += __shfl_down_sync(0xffffffffu, p, off, 8);
    if (ln == 0) {
        float ref = p + bias[n];
        int b = m >> 10, s = m & 1023;
        int h = n / 384, inner = n - h*384, part = inner >> 7, dd = inner & 127;
        const float* src = (part == 0) ? g_q : (part == 1) ? g_k : g_v;
        float got = src[((size_t)(b*H_ + h)*S_ + s)*HD_ + dd];
        if (!(fabsf(got - ref) <= 0.02f + 0.01f*fabsf(ref)))
            g_tilebad[blockIdx.y*TX_ + blockIdx.x] = 1;
    }
}

// ---------------------------------------------------------------------------
// Per-tile fp32 repair (no-op where verified).
// ---------------------------------------------------------------------------
__global__ __launch_bounds__(256) void qkv_fp32(const float* __restrict__ A,
                                                const float* __restrict__ W,
                                                const float* __restrict__ bias) {
    if (!g_tilebad[blockIdx.y*TX_ + blockIdx.x]) return;
    __shared__ float As[8][128];
    __shared__ float Bs[8][128];
    int tid = threadIdx.x;
    int bm = blockIdx.y * 128, bn = blockIdx.x * 128;
    int lr = tid >> 1;
    int lk = (tid & 1) * 4;
    const float* Ap = A + (size_t)(bm + lr) * D_ + lk;
    const float* Wp = W + (size_t)(bn + lr) * D_ + lk;
    int tx = tid & 15, ty = tid >> 4;

    float acc[8][8];
#pragma unroll
    for (int i = 0; i < 8; i++)
#pragma unroll
        for (int j = 0; j < 8; j++) acc[i][j] = 0.f;

    for (int k0 = 0; k0 < D_; k0 += 8) {
        float4 a4 = *(const float4*)(Ap + k0);
        float4 b4 = *(const float4*)(Wp + k0);
        __syncthreads();
        As[lk+0][lr] = a4.x; As[lk+1][lr] = a4.y; As[lk+2][lr] = a4.z; As[lk+3][lr] = a4.w;
        Bs[lk+0][lr] = b4.x; Bs[lk+1][lr] = b4.y; Bs[lk+2][lr] = b4.z; Bs[lk+3][lr] = b4.w;
        __syncthreads();
#pragma unroll
        for (int kk = 0; kk < 8; kk++) {
            float4 a0 = *(const float4*)&As[kk][ty*4];
            float4 a1 = *(const float4*)&As[kk][ty*4 + 64];
            float4 b0 = *(const float4*)&Bs[kk][tx*4];
            float4 b1 = *(const float4*)&Bs[kk][tx*4 + 64];
            float ra[8] = {a0.x,a0.y,a0.z,a0.w,a1.x,a1.y,a1.z,a1.w};
            float rb[8] = {b0.x,b0.y,b0.z,b0.w,b1.x,b1.y,b1.z,b1.w};
#pragma unroll
            for (int i = 0; i < 8; i++)
#pragma unroll
                for (int j = 0; j < 8; j++)
                    acc[i][j] += ra[i] * rb[j];
        }
    }

#pragma unroll
    for (int i = 0; i < 8; i++) {
        int m = bm + ((i < 4) ? ty*4 + i : 64 + ty*4 + (i - 4));
        int b = m >> 10, s = m & 1023;
#pragma unroll
        for (int j = 0; j < 8; j++) {
            int n = bn + ((j < 4) ? tx*4 + j : 64 + tx*4 + (j - 4));
            float v = acc[i][j] + bias[n];
            int h = n / 384;
            int inner = n - h * 384;
            int part = inner >> 7;
            int dd = inner & 127;
            float* dst = (part == 0) ? g_q : (part == 1) ? g_k : g_v;
            dst[((size_t)((b*H_ + h)*S_ + s)) * HD_ + dd] = v;
        }
    }
}

// ---------------------------------------------------------------------------
// q/k: RoPE + (q: 1/sqrt(hd) scale) + bf16 hi/lo split.
// ---------------------------------------------------------------------------
__global__ __launch_bounds__(256) void qk_convert() {
    int i = blockIdx.x * blockDim.x + threadIdx.x;
    const int total = B_ * H_ * S_ * 64;
    if (i >= total) return;
    int j = i & 63;
    int bhs = i >> 6;
    int s = bhs & (S_ - 1);
    float ang = (float)s * exp2f(-(float)j * (13.287712379549449f / 64.f));
    float sn, c;
    sincosf(ang, &sn, &c);
    const float scale = 0.08838834764831845f;

    {
        const float* p = g_q + (size_t)bhs * HD_;
        float x1 = p[j], x2 = p[j + 64];
        float r1 = (x1 * c - x2 * sn) * scale;
        float r2 = (x2 * c + x1 * sn) * scale;
        __nv_bfloat16 h1 = __float2bfloat16_rn(r1);
        __nv_bfloat16 h2 = __float2bfloat16_rn(r2);
        g_qh[(size_t)bhs*HD_ + j]      = h1;
        g_qh[(size_t)bhs*HD_ + j + 64] = h2;
        g_ql[(size_t)bhs*HD_ + j]      = __float2bfloat16_rn(r1 - __bfloat162float(h1));
        g_ql[(size_t)bhs*HD_ + j + 64] = __float2bfloat16_rn(r2 - __bfloat162float(h2));
    }
    {
        const float* p = g_k + (size_t)bhs * HD_;
        float x1 = p[j], x2 = p[j + 64];
        float r1 = x1 * c - x2 * sn;
        float r2 = x2 * c + x1 * sn;
        __nv_bfloat16 h1 = __float2bfloat16_rn(r1);
        __nv_bfloat16 h2 = __float2bfloat16_rn(r2);
        g_kh[(size_t)bhs*HD_ + j]      = h1;
        g_kh[(size_t)bhs*HD_ + j + 64] = h2;
        g_kl[(size_t)bhs*HD_ + j]      = __float2bfloat16_rn(r1 - __bfloat162float(h1));
        g_kl[(size_t)bhs*HD_ + j + 64] = __float2bfloat16_rn(r2 - __bfloat162float(h2));
    }
}

// ---------------------------------------------------------------------------
// v: transpose [s][d] -> [d][s] per (b,h), bf16 hi/lo split.
// ---------------------------------------------------------------------------
__global__ void v_convert(void) {
    __shared__ float tile[32][33];
    int bh = blockIdx.z;
    int s0 = blockIdx.x * 32, d0 = blockIdx.y * 32;
    const float* vb = g_v + (size_t)bh * S_ * HD_;
#pragma unroll
    for (int i = 0; i < 32; i += 8)
        tile[threadIdx.y + i][threadIdx.x] =
            vb[(size_t)(s0 + threadIdx.y + i) * HD_ + d0 + threadIdx.x];
    __syncthreads();
#pragma unroll
    for (int i = 0; i < 32; i += 8) {
        int d = d0 + threadIdx.y + i, sx = s0 + threadIdx.x;
        float v = tile[threadIdx.x][threadIdx.y + i];
        __nv_bfloat16 h = __float2bfloat16_rn(v);
        size_t o = ((size_t)bh * HD_ + d) * S_ + sx;
        g_vth[o] = h;
        g_vtl[o] = __float2bfloat16_rn(v - __bfloat162float(h));
    }
}

// ---------------------------------------------------------------------------
// Causal flash attention via mma.sync bf16x3.
// CTA = (64 q-rows, bh). 256 thr / 8 warps.
// QK: warps 0-3 k-dims [0,64), warps 4-7 [64,128); each warp 16 rows x 64 cols
//     (8 accs, same-acc mma distance 8). Partials in ScA/ScB, summed in softmax.
// PV: warp (wr=wid&3, wc=wid>>2): rows 16wr..+15, cols 64wc..+63 (8 accs).
// ---------------------------------------------------------------------------
#define RSA 136   // q/k smem row stride (bf16)
#define RSV 72    // vT / P smem row stride (bf16)
#define ATTN_SMEM 158976

__global__ __launch_bounds__(256) void attn_mma(float* __restrict__ out) {
    extern __shared__ char smraw[];
    __nv_bfloat16* sQh = (__nv_bfloat16*)smraw;
    __nv_bfloat16* sQl = sQh + 64*RSA;
    __nv_bfloat16* sKh = sQl + 64*RSA;
    __nv_bfloat16* sKl = sKh + 64*RSA;
    __nv_bfloat16* sVh = sKl + 64*RSA;
    __nv_bfloat16* sVl = sVh + 128*RSV;
    __nv_bfloat16* sPh = sVl + 128*RSV;
    __nv_bfloat16* sPl = sPh + 64*RSV;
    float* ScA  = (float*)(sPl + 64*RSV);
    float* ScB  = ScA + 64*65;
    float* rowm = ScB + 64*65;
    float* rowl = rowm + 64;
    float* corr = rowl + 64;

    int tid = threadIdx.x, wid = tid >> 5, lid = tid & 31;
    int qt = blockIdx.x, bh = blockIdx.y, q0 = qt * 64;
    int qr = lid >> 2, kp = (lid & 3) * 2;

    const __nv_bfloat16* Qhg = g_qh + (size_t)(bh*S_ + q0) * HD_;
    const __nv_bfloat16* Qlg = g_ql + (size_t)(bh*S_ + q0) * HD_;

    // load Q tile (64 x 128), 16B chunks
#pragma unroll
    for (int t = 0; t < 4; t++) {
        int ch = tid + t * 256;
        int r = ch >> 4, c8 = (ch & 15) * 8;
        *(float4*)(sQh + r*RSA + c8) = *(const float4*)(Qhg + r*HD_ + c8);
        *(float4*)(sQl + r*RSA + c8) = *(const float4*)(Qlg + r*HD_ + c8);
    }
    if (tid < 64) { rowm[tid] = -1e30f; rowl[tid] = 0.f; }

    float o[8][4];
#pragma unroll
    for (int i = 0; i < 8; i++)
#pragma unroll
        for (int j = 0; j < 4; j++) o[i][j] = 0.f;

    int wrS = wid & 3, gS = wid >> 2;
    int wrP = wid & 3, wcP = wid >> 2;
    float* ScW = gS ? ScB : ScA;

    for (int kt = 0; kt <= qt; kt++) {
        int k0 = kt * 64;
        __syncthreads();
        // stage K (64x128) and Vt (128x64)
#pragma unroll
        for (int t = 0; t < 4; t++) {
            int ch = tid + t * 256;
            int r = ch >> 4, c8 = (ch & 15) * 8;
            size_t go = (size_t)(bh*S_ + k0 + r) * HD_ + c8;
            *(float4*)(sKh + r*RSA + c8) = *(const float4*)(g_kh + go);
            *(float4*)(sKl + r*RSA + c8) = *(const float4*)(g_kl + go);
        }
#pragma unroll
        for (int t = 0; t < 4; t++) {
            int ch = tid + t * 256;
            int r = ch >> 3, c8 = (ch & 7) * 8;
            size_t go = ((size_t)bh*HD_ + r) * S_ + k0 + c8;
            *(float4*)(sVh + r*RSV + c8) = *(const float4*)(g_vth + go);
            *(float4*)(sVl + r*RSV + c8) = *(const float4*)(g_vtl + go);
        }
        __syncthreads();

        // ---- QK^T ----
        float sc[8][4];
#pragma unroll
        for (int i = 0; i < 8; i++)
#pragma unroll
            for (int j = 0; j < 4; j++) sc[i][j] = 0.f;

#pragma unroll
        for (int ks = 0; ks < 4; ks++) {
            int kb = gS*64 + ks*16 + kp;
            uint32_t aH[4], aL[4], bH[8][2], bL[8][2];
            int oa = (wrS*16 + qr) * RSA + kb;
            aH[0] = *(const uint32_t*)(sQh + oa);
            aH[1] = *(const uint32_t*)(sQh + oa + 8*RSA);
            aH[2] = *(const uint32_t*)(sQh + oa + 8);
            aH[3] = *(const uint32_t*)(sQh + oa + 8*RSA + 8);
            aL[0] = *(const uint32_t*)(sQl + oa);
            aL[1] = *(const uint32_t*)(sQl + oa + 8*RSA);
            aL[2] = *(const uint32_t*)(sQl + oa + 8);
            aL[3] = *(const uint32_t*)(sQl + oa + 8*RSA + 8);
#pragma unroll
            for (int nt = 0; nt < 8; nt++) {
                int ob = (nt*8 + qr) * RSA + kb;
                bH[nt][0] = *(const uint32_t*)(sKh + ob);
                bH[nt][1] = *(const uint32_t*)(sKh + ob + 8);
                bL[nt][0] = *(const uint32_t*)(sKl + ob);
                bL[nt][1] = *(const uint32_t*)(sKl + ob + 8);
            }
#pragma unroll
            for (int nt = 0; nt < 8; nt++) mma_bf16(sc[nt], aH, bH[nt]);
#pragma unroll
            for (int nt = 0; nt < 8; nt++) mma_bf16(sc[nt], aH, bL[nt]);
#pragma unroll
            for (int nt = 0; nt < 8; nt++) mma_bf16(sc[nt], aL, bH[nt]);
        }
#pragma unroll
        for (int nt = 0; nt < 8; nt++)
#pragma unroll
            for (int t = 0; t < 4; t++) {
                int r = wrS*16 + qr + ((t >= 2) ? 8 : 0);
                int c = nt*8 + kp + (t & 1);
                ScW[r*65 + c] = sc[nt][t];
            }
        __syncthreads();

        // ---- softmax + P split (64 threads, 1 row each) ----
        if (tid < 64) {
            int r = tid;
            bool diag = (kt == qt);
            float mo = rowm[r], mx = mo;
#pragma unroll 8
            for (int c = 0; c < 64; c++) {
                float v = (diag && c > r) ? -1e30f : ScA[r*65+c] + ScB[r*65+c];
                mx = fmaxf(mx, v);
            }
            float co = __expf(mo - mx);
            float su = 0.f;
#pragma unroll 8
            for (int c = 0; c < 64; c++) {
                float v = (diag && c > r) ? -1e30f : ScA[r*65+c] + ScB[r*65+c];
                float p = __expf(v - mx);
                su += p;
                __nv_bfloat16 ph = __float2bfloat16_rn(p);
                sPh[r*RSV + c] = ph;
                sPl[r*RSV + c] = __float2bfloat16_rn(p - __bfloat162float(ph));
            }
            rowl[r] = rowl[r] * co + su;
            rowm[r] = mx;
            corr[r] = co;
        }
        __syncthreads();

        // ---- O = O*corr + P V ----
        float co1 = corr[wrP*16 + qr], co2 = corr[wrP*16 + qr + 8];
#pragma unroll
        for (int nt = 0; nt < 8; nt++) {
            o[nt][0] *= co1; o[nt][1] *= co1;
            o[nt][2] *= co2; o[nt][3] *= co2;
        }
#pragma unroll
        for (int ks = 0; ks < 4; ks++) {
            int kb = ks*16 + kp;
            uint32_t aH[4], aL[4], bH[8][2], bL[8][2];
            int oa = (wrP*16 + qr) * RSV + kb;
            aH[0] = *(const uint32_t*)(sPh + oa);
            aH[1] = *(const uint32_t*)(sPh + oa + 8*RSV);
            aH[2] = *(const uint32_t*)(sPh + oa + 8);
            aH[3] = *(const uint32_t*)(sPh + oa + 8*RSV + 8);
            aL[0] = *(const uint32_t*)(sPl + oa);
            aL[1] = *(const uint32_t*)(sPl + oa + 8*RSV);
            aL[2] = *(const uint32_t*)(sPl + oa + 8);
            aL[3] = *(const uint32_t*)(sPl + oa + 8*RSV + 8);
#pragma unroll
            for (int nt = 0; nt < 8; nt++) {
                int ob = (wcP*64 + nt*8 + qr) * RSV + kb;
                bH[nt][0] = *(const uint32_t*)(sVh + ob);
                bH[nt][1] = *(const uint32_t*)(sVh + ob + 8);
                bL[nt][0] = *(const uint32_t*)(sVl + ob);
                bL[nt][1] = *(const uint32_t*)(sVl + ob + 8);
            }
#pragma unroll
            for (int nt = 0; nt < 8; nt++) mma_bf16(o[nt], aH, bH[nt]);
#pragma unroll
            for (int nt = 0; nt < 8; nt++) mma_bf16(o[nt], aH, bL[nt]);
#pragma unroll
            for (int nt = 0; nt < 8; nt++) mma_bf16(o[nt], aL, bH[nt]);
        }
    }

    int rA = wrP*16 + qr, rB = rA + 8;
    float i1 = 1.f / rowl[rA], i2 = 1.f / rowl[rB];
    int b = bh >> 4, h = bh & 15;
#pragma unroll
    for (int nt = 0; nt < 8; nt++) {
        int col = wcP*64 + nt*8 + kp;
        float2 v0 = { o[nt][0]*i1, o[nt][1]*i1 };
        *(float2*)&out[((size_t)(b*S_ + q0 + rA))*D_ + h*HD_ + col] = v0;
        float2 v1 = { o[nt][2]*i2, o[nt][3]*i2 };
        *(float2*)&out[((size_t)(b*S_ + q0 + rB))*D_ + h*HD_ + col] = v1;
    }
}

// ---------------------------------------------------------------------------
extern "C" void kernel_launch(void* const* d_in, const int* in_sizes, int n_in,
                              void* d_out, int out_size) {
    const float* hidden = (const float*)d_in[0];
    const float* w_qkv  = (const float*)d_in[1];
    const float* b_qkv  = (const float*)d_in[2];
    float* out = (float*)d_out;

    cudaFuncSetAttribute(attn_mma, cudaFuncAttributeMaxDynamicSharedMemorySize,
                         ATTN_SMEM);

    reset_flags<<<6, 256>>>();
    split_all<<<5120, 256>>>(hidden, w_qkv);
    qkv_mma<<<dim3(TX_, TY_), 256, GEMM_SMEM>>>(b_qkv);
    verify_tiles<<<dim3(TX_, TY_), 256>>>(hidden, w_qkv, b_qkv);
    qkv_fp32<<<dim3(TX_, TY_), 256>>>(hidden, w_qkv, b_qkv);

    int total = B_ * H_ * S_ * 64;
    qk_convert<<<(total + 255) / 256, 256>>>();
    v_convert<<<dim3(S_/32, HD_/32, B_*H_), dim3(32, 8)>>>();

    attn_mma<<<dim3(S_ / 64, B_ * H_), 256, ATTN_SMEM>>>(out);
}

// round 15
// speedup vs baseline: 3.1573x; 1.3944x over previous
#include <cuda_runtime.h>
#include <cuda_bf16.h>
#include <cstdint>

#define B_  4
#define S_  1024
#define D_  2048
#define H_  16
#define HD_ 128

#define MA_ (B_*S_)    // 4096
#define NA_ (3*D_)     // 6144
#define KA_ D_         // 2048

#define TX_ 48
#define TY_ 32

// Scratch (allocation-free rule)
__device__ float g_q[B_*H_*S_*HD_];
__device__ float g_k[B_*H_*S_*HD_];
__device__ float g_v[B_*H_*S_*HD_];
__device__ __align__(16) __nv_bfloat16 g_ah[(size_t)MA_*KA_];
__device__ __align__(16) __nv_bfloat16 g_al[(size_t)MA_*KA_];
__device__ __align__(16) __nv_bfloat16 g_wh[(size_t)NA_*KA_];
__device__ __align__(16) __nv_bfloat16 g_wl[(size_t)NA_*KA_];
// attention bf16 operands (q/k: [b,h,s,d]; v transposed: [b,h,d,s])
__device__ __align__(16) __nv_bfloat16 g_qh[B_*H_*S_*HD_];
__device__ __align__(16) __nv_bfloat16 g_ql[B_*H_*S_*HD_];
__device__ __align__(16) __nv_bfloat16 g_kh[B_*H_*S_*HD_];
__device__ __align__(16) __nv_bfloat16 g_kl[B_*H_*S_*HD_];
__device__ __align__(16) __nv_bfloat16 g_vth[B_*H_*S_*HD_];
__device__ __align__(16) __nv_bfloat16 g_vtl[B_*H_*S_*HD_];
__device__ int g_tilebad[TY_*TX_];

__device__ __forceinline__ void mma_bf16(float c[4], const uint32_t a[4],
                                         const uint32_t b[2]) {
    asm volatile("mma.sync.aligned.m16n8k16.row.col.f32.bf16.bf16.f32 "
        "{%0,%1,%2,%3}, {%4,%5,%6,%7}, {%8,%9}, {%0,%1,%2,%3};"
        : "+f"(c[0]), "+f"(c[1]), "+f"(c[2]), "+f"(c[3])
        : "r"(a[0]), "r"(a[1]), "r"(a[2]), "r"(a[3]), "r"(b[0]), "r"(b[1]));
}

__device__ __forceinline__ void split4(float4 v, __nv_bfloat16* hp,
                                       __nv_bfloat16* lp, int off) {
    __nv_bfloat16 h0 = __float2bfloat16_rn(v.x);
    __nv_bfloat16 h1 = __float2bfloat16_rn(v.y);
    __nv_bfloat16 h2 = __float2bfloat16_rn(v.z);
    __nv_bfloat16 h3 = __float2bfloat16_rn(v.w);
    __nv_bfloat16 l0 = __float2bfloat16_rn(v.x - __bfloat162float(h0));
    __nv_bfloat16 l1 = __float2bfloat16_rn(v.y - __bfloat162float(h1));
    __nv_bfloat16 l2 = __float2bfloat16_rn(v.z - __bfloat162float(h2));
    __nv_bfloat16 l3 = __float2bfloat16_rn(v.w - __bfloat162float(h3));
    ((__nv_bfloat162*)hp)[2*off+0] = __halves2bfloat162(h0, h1);
    ((__nv_bfloat162*)hp)[2*off+1] = __halves2bfloat162(h2, h3);
    ((__nv_bfloat162*)lp)[2*off+0] = __halves2bfloat162(l0, l1);
    ((__nv_bfloat162*)lp)[2*off+1] = __halves2bfloat162(l2, l3);
}

// ---------------------------------------------------------------------------
__global__ void reset_flags() {
    int i = blockIdx.x * 256 + threadIdx.x;
    if (i < TY_*TX_) g_tilebad[i] = 0;
}

#define N4A (MA_*KA_/4)
__global__ __launch_bounds__(256) void split_all(const float* __restrict__ hidden,
                                                 const float* __restrict__ w) {
    int i4 = blockIdx.x * 256 + threadIdx.x;
    int base = i4 * 4;
    const float* src; __nv_bfloat16 *hp, *lp; int off;
    if (base < N4A) { src = hidden; hp = g_ah; lp = g_al; off = base; }
    else            { src = w;      hp = g_wh; lp = g_wl; off = base - N4A; }
    float4 v[4];
#pragma unroll
    for (int t = 0; t < 4; t++) v[t] = ((const float4*)src)[off + t];
#pragma unroll
    for (int t = 0; t < 4; t++) split4(v[t], hp, lp, off + t);
}

// ---------------------------------------------------------------------------
// bf16x3 QKV GEMM via mma.sync (validated: term-outer ordering).
// ---------------------------------------------------------------------------
#define RS   40
#define ARR  (128*RS)
#define GEMM_SMEM (4*ARR*2)      // 40960 bytes

__global__ __launch_bounds__(256) void qkv_mma(const float* __restrict__ bias) {
    extern __shared__ __nv_bfloat16 sh[];

    int tid = threadIdx.x;
    int wid = tid >> 5, lid = tid & 31;
    int bn = blockIdx.x * 128, bm = blockIdx.y * 128;
    int wm = wid & 1, wn = wid >> 1;
    int qr = lid >> 2;
    int kp = (lid & 3) * 2;

    const __nv_bfloat16* baseA_h = g_ah + (size_t)bm * KA_;
    const __nv_bfloat16* baseA_l = g_al + (size_t)bm * KA_;
    const __nv_bfloat16* baseW_h = g_wh + (size_t)bn * KA_;
    const __nv_bfloat16* baseW_l = g_wl + (size_t)bn * KA_;

    int ldr = tid >> 2, ldc = tid & 3;

    float acc[4][4][4];
#pragma unroll
    for (int i = 0; i < 4; i++)
#pragma unroll
        for (int j = 0; j < 4; j++)
#pragma unroll
            for (int k = 0; k < 4; k++) acc[i][j][k] = 0.f;

    float4 stg[8];
#pragma unroll
    for (int t = 0; t < 2; t++) {
        int r = ldr + t * 64;
        size_t go = (size_t)r * KA_ + ldc * 8;
        stg[0*2+t] = *(const float4*)(baseA_h + go);
        stg[1*2+t] = *(const float4*)(baseA_l + go);
        stg[2*2+t] = *(const float4*)(baseW_h + go);
        stg[3*2+t] = *(const float4*)(baseW_l + go);
    }

    const int NITER = KA_ / 32;
    for (int it = 0; it < NITER; it++) {
        __syncthreads();
#pragma unroll
        for (int arr = 0; arr < 4; arr++)
#pragma unroll
            for (int t = 0; t < 2; t++) {
                int r = ldr + t * 64;
                *(float4*)(sh + arr*ARR + r*RS + ldc*8) = stg[arr*2 + t];
            }
        __syncthreads();
        if (it + 1 < NITER) {
            int k0 = (it + 1) * 32;
#pragma unroll
            for (int t = 0; t < 2; t++) {
                int r = ldr + t * 64;
                size_t go = (size_t)r * KA_ + k0 + ldc * 8;
                stg[0*2+t] = *(const float4*)(baseA_h + go);
                stg[1*2+t] = *(const float4*)(baseA_l + go);
                stg[2*2+t] = *(const float4*)(baseW_h + go);
                stg[3*2+t] = *(const float4*)(baseW_l + go);
            }
        }

        const __nv_bfloat16* sAh = sh;
        const __nv_bfloat16* sAl = sh + ARR;
        const __nv_bfloat16* sWh = sh + 2*ARR;
        const __nv_bfloat16* sWl = sh + 3*ARR;

#pragma unroll
        for (int ks = 0; ks < 2; ks++) {
            int kb = ks * 16 + kp;
            uint32_t aHf[4][4], aLf[4][4], bHf[4][2], bLf[4][2];
#pragma unroll
            for (int am = 0; am < 4; am++) {
                int o = (wm*64 + am*16 + qr) * RS + kb;
                aHf[am][0] = *(const uint32_t*)(sAh + o);
                aHf[am][1] = *(const uint32_t*)(sAh + o + 8*RS);
                aHf[am][2] = *(const uint32_t*)(sAh + o + 8);
                aHf[am][3] = *(const uint32_t*)(sAh + o + 8*RS + 8);
                aLf[am][0] = *(const uint32_t*)(sAl + o);
                aLf[am][1] = *(const uint32_t*)(sAl + o + 8*RS);
                aLf[am][2] = *(const uint32_t*)(sAl + o + 8);
                aLf[am][3] = *(const uint32_t*)(sAl + o + 8*RS + 8);
            }
#pragma unroll
            for (int nb = 0; nb < 4; nb++) {
                int o = (wn*32 + nb*8 + qr) * RS + kb;
                bHf[nb][0] = *(const uint32_t*)(sWh + o);
                bHf[nb][1] = *(const uint32_t*)(sWh + o + 8);
                bLf[nb][0] = *(const uint32_t*)(sWl + o);
                bLf[nb][1] = *(const uint32_t*)(sWl + o + 8);
            }
#pragma unroll
            for (int am = 0; am < 4; am++)
#pragma unroll
                for (int nb = 0; nb < 4; nb++)
                    mma_bf16(acc[am][nb], aHf[am], bHf[nb]);
#pragma unroll
            for (int am = 0; am < 4; am++)
#pragma unroll
                for (int nb = 0; nb < 4; nb++)
                    mma_bf16(acc[am][nb], aHf[am], bLf[nb]);
#pragma unroll
            for (int am = 0; am < 4; am++)
#pragma unroll
                for (int nb = 0; nb < 4; nb++)
                    mma_bf16(acc[am][nb], aLf[am], bHf[nb]);
        }
    }

    int b = bm >> 10;
#pragma unroll
    for (int am = 0; am < 4; am++) {
        int s0 = (bm & 1023) + wm * 64 + am * 16 + qr;
#pragma unroll
        for (int nb = 0; nb < 4; nb++) {
            int n0    = bn + wn * 32 + nb * 8;
            int h     = n0 / 384;
            int inner = n0 - h * 384;
            int part  = inner >> 7;
            int dd    = (inner & 127) + kp;
            float* dst = (part == 0) ? g_q : (part == 1) ? g_k : g_v;
            float b0v = bias[n0 + kp], b1v = bias[n0 + kp + 1];
            size_t rb = ((size_t)(b * H_ + h) * S_);
            float2 v0 = { acc[am][nb][0] + b0v, acc[am][nb][1] + b1v };
            *(float2*)&dst[(rb + s0) * HD_ + dd] = v0;
            float2 v1 = { acc[am][nb][2] + b0v, acc[am][nb][3] + b1v };
            *(float2*)&dst[(rb + s0 + 8) * HD_ + dd] = v1;
        }
    }
}

// ---------------------------------------------------------------------------
// Light verify: 1 sample per tile, block-wide coalesced dot (256 thr).
// A tile-wide mma corruption corrupts every fragment -> 1 sample suffices.
// ---------------------------------------------------------------------------
__global__ __launch_bounds__(256) void verify_tiles(const float* __restrict__ hidden,
                                                    const float* __restrict__ w,
                                                    const float* __restrict__ bias) {
    __shared__ float red[8];
    int tile = blockIdx.x;            // 0..1535
    int ty = tile / TX_, tx = tile - ty * TX_;
    int m = ty * 128 + ((tile*37 + 11) & 127);
    int n = tx * 128 + ((tile*53 + 7) & 127);
    int t = threadIdx.x;
    const float* hr = hidden + (size_t)m * KA_;
    const float* wr = w + (size_t)n * KA_;
    float p = 0.f;
#pragma unroll
    for (int k = t; k < KA_; k += 256) p += hr[k] * wr[k];
#pragma unroll
    for (int off = 16; off > 0; off >>= 1)
        p += __shfl_down_sync(0xffffffffu, p, off);
    if ((t & 31) == 0) red[t >> 5] = p;
    __syncthreads();
    if (t == 0) {
        float ref = bias[n];
#pragma unroll
        for (int i = 0; i < 8; i++) ref += red[i];
        int b = m >> 10, s = m & 1023;
        int h = n / 384, inner = n - h*384, part = inner >> 7, dd = inner & 127;
        const float* src = (part == 0) ? g_q : (part == 1) ? g_k : g_v;
        float got = src[((size_t)(b*H_ + h)*S_ + s)*HD_ + dd];
        if (!(fabsf(got - ref) <= 0.02f + 0.01f*fabsf(ref)))
            g_tilebad[tile] = 1;
    }
}

// ---------------------------------------------------------------------------
// Per-tile fp32 repair (no-op where verified).
// ---------------------------------------------------------------------------
__global__ __launch_bounds__(256) void qkv_fp32(const float* __restrict__ A,
                                                const float* __restrict__ W,
                                                const float* __restrict__ bias) {
    if (!g_tilebad[blockIdx.y*TX_ + blockIdx.x]) return;
    __shared__ float As[8][128];
    __shared__ float Bs[8][128];
    int tid = threadIdx.x;
    int bm = blockIdx.y * 128, bn = blockIdx.x * 128;
    int lr = tid >> 1;
    int lk = (tid & 1) * 4;
    const float* Ap = A + (size_t)(bm + lr) * D_ + lk;
    const float* Wp = W + (size_t)(bn + lr) * D_ + lk;
    int tx = tid & 15, ty = tid >> 4;

    float acc[8][8];
#pragma unroll
    for (int i = 0; i < 8; i++)
#pragma unroll
        for (int j = 0; j < 8; j++) acc[i][j] = 0.f;

    for (int k0 = 0; k0 < D_; k0 += 8) {
        float4 a4 = *(const float4*)(Ap + k0);
        float4 b4 = *(const float4*)(Wp + k0);
        __syncthreads();
        As[lk+0][lr] = a4.x; As[lk+1][lr] = a4.y; As[lk+2][lr] = a4.z; As[lk+3][lr] = a4.w;
        Bs[lk+0][lr] = b4.x; Bs[lk+1][lr] = b4.y; Bs[lk+2][lr] = b4.z; Bs[lk+3][lr] = b4.w;
        __syncthreads();
#pragma unroll
        for (int kk = 0; kk < 8; kk++) {
            float4 a0 = *(const float4*)&As[kk][ty*4];
            float4 a1 = *(const float4*)&As[kk][ty*4 + 64];
            float4 b0 = *(const float4*)&Bs[kk][tx*4];
            float4 b1 = *(const float4*)&Bs[kk][tx*4 + 64];
            float ra[8] = {a0.x,a0.y,a0.z,a0.w,a1.x,a1.y,a1.z,a1.w};
            float rb[8] = {b0.x,b0.y,b0.z,b0.w,b1.x,b1.y,b1.z,b1.w};
#pragma unroll
            for (int i = 0; i < 8; i++)
#pragma unroll
                for (int j = 0; j < 8; j++)
                    acc[i][j] += ra[i] * rb[j];
        }
    }

#pragma unroll
    for (int i = 0; i < 8; i++) {
        int m = bm + ((i < 4) ? ty*4 + i : 64 + ty*4 + (i - 4));
        int b = m >> 10, s = m & 1023;
#pragma unroll
        for (int j = 0; j < 8; j++) {
            int n = bn + ((j < 4) ? tx*4 + j : 64 + tx*4 + (j - 4));
            float v = acc[i][j] + bias[n];
            int h = n / 384;
            int inner = n - h * 384;
            int part = inner >> 7;
            int dd = inner & 127;
            float* dst = (part == 0) ? g_q : (part == 1) ? g_k : g_v;
            dst[((size_t)((b*H_ + h)*S_ + s)) * HD_ + dd] = v;
        }
    }
}

// ---------------------------------------------------------------------------
// q/k: RoPE + (q: 1/sqrt(hd) scale) + bf16 hi/lo split.
// ---------------------------------------------------------------------------
__global__ __launch_bounds__(256) void qk_convert() {
    int i = blockIdx.x * blockDim.x + threadIdx.x;
    const int total = B_ * H_ * S_ * 64;
    if (i >= total) return;
    int j = i & 63;
    int bhs = i >> 6;
    int s = bhs & (S_ - 1);
    float ang = (float)s * exp2f(-(float)j * (13.287712379549449f / 64.f));
    float sn, c;
    sincosf(ang, &sn, &c);
    const float scale = 0.08838834764831845f;

    {
        const float* p = g_q + (size_t)bhs * HD_;
        float x1 = p[j], x2 = p[j + 64];
        float r1 = (x1 * c - x2 * sn) * scale;
        float r2 = (x2 * c + x1 * sn) * scale;
        __nv_bfloat16 h1 = __float2bfloat16_rn(r1);
        __nv_bfloat16 h2 = __float2bfloat16_rn(r2);
        g_qh[(size_t)bhs*HD_ + j]      = h1;
        g_qh[(size_t)bhs*HD_ + j + 64] = h2;
        g_ql[(size_t)bhs*HD_ + j]      = __float2bfloat16_rn(r1 - __bfloat162float(h1));
        g_ql[(size_t)bhs*HD_ + j + 64] = __float2bfloat16_rn(r2 - __bfloat162float(h2));
    }
    {
        const float* p = g_k + (size_t)bhs * HD_;
        float x1 = p[j], x2 = p[j + 64];
        float r1 = x1 * c - x2 * sn;
        float r2 = x2 * c + x1 * sn;
        __nv_bfloat16 h1 = __float2bfloat16_rn(r1);
        __nv_bfloat16 h2 = __float2bfloat16_rn(r2);
        g_kh[(size_t)bhs*HD_ + j]      = h1;
        g_kh[(size_t)bhs*HD_ + j + 64] = h2;
        g_kl[(size_t)bhs*HD_ + j]      = __float2bfloat16_rn(r1 - __bfloat162float(h1));
        g_kl[(size_t)bhs*HD_ + j + 64] = __float2bfloat16_rn(r2 - __bfloat162float(h2));
    }
}

// ---------------------------------------------------------------------------
// v: transpose [s][d] -> [d][s] per (b,h), bf16 hi/lo split.
// ---------------------------------------------------------------------------
__global__ void v_convert(void) {
    __shared__ float tile[32][33];
    int bh = blockIdx.z;
    int s0 = blockIdx.x * 32, d0 = blockIdx.y * 32;
    const float* vb = g_v + (size_t)bh * S_ * HD_;
#pragma unroll
    for (int i = 0; i < 32; i += 8)
        tile[threadIdx.y + i][threadIdx.x] =
            vb[(size_t)(s0 + threadIdx.y + i) * HD_ + d0 + threadIdx.x];
    __syncthreads();
#pragma unroll
    for (int i = 0; i < 32; i += 8) {
        int d = d0 + threadIdx.y + i, sx = s0 + threadIdx.x;
        float v = tile[threadIdx.x][threadIdx.y + i];
        __nv_bfloat16 h = __float2bfloat16_rn(v);
        size_t o = ((size_t)bh * HD_ + d) * S_ + sx;
        g_vth[o] = h;
        g_vtl[o] = __float2bfloat16_rn(v - __bfloat162float(h));
    }
}

// ---------------------------------------------------------------------------
// Causal flash attention via mma.sync bf16x3 (validated R12).
// ---------------------------------------------------------------------------
#define RSA 136   // q/k smem row stride (bf16)
#define RSV 72    // vT / P smem row stride (bf16)
#define ATTN_SMEM 158976

__global__ __launch_bounds__(256) void attn_mma(float* __restrict__ out) {
    extern __shared__ char smraw[];
    __nv_bfloat16* sQh = (__nv_bfloat16*)smraw;
    __nv_bfloat16* sQl = sQh + 64*RSA;
    __nv_bfloat16* sKh = sQl + 64*RSA;
    __nv_bfloat16* sKl = sKh + 64*RSA;
    __nv_bfloat16* sVh = sKl + 64*RSA;
    __nv_bfloat16* sVl = sVh + 128*RSV;
    __nv_bfloat16* sPh = sVl + 128*RSV;
    __nv_bfloat16* sPl = sPh + 64*RSV;
    float* ScA  = (float*)(sPl + 64*RSV);
    float* ScB  = ScA + 64*65;
    float* rowm = ScB + 64*65;
    float* rowl = rowm + 64;
    float* corr = rowl + 64;

    int tid = threadIdx.x, wid = tid >> 5, lid = tid & 31;
    int qt = blockIdx.x, bh = blockIdx.y, q0 = qt * 64;
    int qr = lid >> 2, kp = (lid & 3) * 2;

    const __nv_bfloat16* Qhg = g_qh + (size_t)(bh*S_ + q0) * HD_;
    const __nv_bfloat16* Qlg = g_ql + (size_t)(bh*S_ + q0) * HD_;

#pragma unroll
    for (int t = 0; t < 4; t++) {
        int ch = tid + t * 256;
        int r = ch >> 4, c8 = (ch & 15) * 8;
        *(float4*)(sQh + r*RSA + c8) = *(const float4*)(Qhg + r*HD_ + c8);
        *(float4*)(sQl + r*RSA + c8) = *(const float4*)(Qlg + r*HD_ + c8);
    }
    if (tid < 64) { rowm[tid] = -1e30f; rowl[tid] = 0.f; }

    float o[8][4];
#pragma unroll
    for (int i = 0; i < 8; i++)
#pragma unroll
        for (int j = 0; j < 4; j++) o[i][j] = 0.f;

    int wrS = wid & 3, gS = wid >> 2;
    int wrP = wid & 3, wcP = wid >> 2;
    float* ScW = gS ? ScB : ScA;

    for (int kt = 0; kt <= qt; kt++) {
        int k0 = kt * 64;
        __syncthreads();
#pragma unroll
        for (int t = 0; t < 4; t++) {
            int ch = tid + t * 256;
            int r = ch >> 4, c8 = (ch & 15) * 8;
            size_t go = (size_t)(bh*S_ + k0 + r) * HD_ + c8;
            *(float4*)(sKh + r*RSA + c8) = *(const float4*)(g_kh + go);
            *(float4*)(sKl + r*RSA + c8) = *(const float4*)(g_kl + go);
        }
#pragma unroll
        for (int t = 0; t < 4; t++) {
            int ch = tid + t * 256;
            int r = ch >> 3, c8 = (ch & 7) * 8;
            size_t go = ((size_t)bh*HD_ + r) * S_ + k0 + c8;
            *(float4*)(sVh + r*RSV + c8) = *(const float4*)(g_vth + go);
            *(float4*)(sVl + r*RSV + c8) = *(const float4*)(g_vtl + go);
        }
        __syncthreads();

        // ---- QK^T ----
        float sc[8][4];
#pragma unroll
        for (int i = 0; i < 8; i++)
#pragma unroll
            for (int j = 0; j < 4; j++) sc[i][j] = 0.f;

#pragma unroll
        for (int ks = 0; ks < 4; ks++) {
            int kb = gS*64 + ks*16 + kp;
            uint32_t aH[4], aL[4], bH[8][2], bL[8][2];
            int oa = (wrS*16 + qr) * RSA + kb;
            aH[0] = *(const uint32_t*)(sQh + oa);
            aH[1] = *(const uint32_t*)(sQh + oa + 8*RSA);
            aH[2] = *(const uint32_t*)(sQh + oa + 8);
            aH[3] = *(const uint32_t*)(sQh + oa + 8*RSA + 8);
            aL[0] = *(const uint32_t*)(sQl + oa);
            aL[1] = *(const uint32_t*)(sQl + oa + 8*RSA);
            aL[2] = *(const uint32_t*)(sQl + oa + 8);
            aL[3] = *(const uint32_t*)(sQl + oa + 8*RSA + 8);
#pragma unroll
            for (int nt = 0; nt < 8; nt++) {
                int ob = (nt*8 + qr) * RSA + kb;
                bH[nt][0] = *(const uint32_t*)(sKh + ob);
                bH[nt][1] = *(const uint32_t*)(sKh + ob + 8);
                bL[nt][0] = *(const uint32_t*)(sKl + ob);
                bL[nt][1] = *(const uint32_t*)(sKl + ob + 8);
            }
#pragma unroll
            for (int nt = 0; nt < 8; nt++) mma_bf16(sc[nt], aH, bH[nt]);
#pragma unroll
            for (int nt = 0; nt < 8; nt++) mma_bf16(sc[nt], aH, bL[nt]);
#pragma unroll
            for (int nt = 0; nt < 8; nt++) mma_bf16(sc[nt], aL, bH[nt]);
        }
#pragma unroll
        for (int nt = 0; nt < 8; nt++)
#pragma unroll
            for (int t = 0; t < 4; t++) {
                int r = wrS*16 + qr + ((t >= 2) ? 8 : 0);
                int c = nt*8 + kp + (t & 1);
                ScW[r*65 + c] = sc[nt][t];
            }
        __syncthreads();

        // ---- softmax + P split ----
        if (tid < 64) {
            int r = tid;
            bool diag = (kt == qt);
            float mo = rowm[r], mx = mo;
#pragma unroll 8
            for (int c = 0; c < 64; c++) {
                float v = (diag && c > r) ? -1e30f : ScA[r*65+c] + ScB[r*65+c];
                mx = fmaxf(mx, v);
            }
            float co = __expf(mo - mx);
            float su = 0.f;
#pragma unroll 8
            for (int c = 0; c < 64; c++) {
                float v = (diag && c > r) ? -1e30f : ScA[r*65+c] + ScB[r*65+c];
                float p = __expf(v - mx);
                su += p;
                __nv_bfloat16 ph = __float2bfloat16_rn(p);
                sPh[r*RSV + c] = ph;
                sPl[r*RSV + c] = __float2bfloat16_rn(p - __bfloat162float(ph));
            }
            rowl[r] = rowl[r] * co + su;
            rowm[r] = mx;
            corr[r] = co;
        }
        __syncthreads();

        // ---- O = O*corr + P V ----
        float co1 = corr[wrP*16 + qr], co2 = corr[wrP*16 + qr + 8];
#pragma unroll
        for (int nt = 0; nt < 8; nt++) {
            o[nt][0] *= co1; o[nt][1] *= co1;
            o[nt][2] *= co2; o[nt][3] *= co2;
        }
#pragma unroll
        for (int ks = 0; ks < 4; ks++) {
            int kb = ks*16 + kp;
            uint32_t aH[4], aL[4], bH[8][2], bL[8][2];
            int oa = (wrP*16 + qr) * RSV + kb;
            aH[0] = *(const uint32_t*)(sPh + oa);
            aH[1] = *(const uint32_t*)(sPh + oa + 8*RSV);
            aH[2] = *(const uint32_t*)(sPh + oa + 8);
            aH[3] = *(const uint32_t*)(sPh + oa + 8*RSV + 8);
            aL[0] = *(const uint32_t*)(sPl + oa);
            aL[1] = *(const uint32_t*)(sPl + oa + 8*RSV);
            aL[2] = *(const uint32_t*)(sPl + oa + 8);
            aL[3] = *(const uint32_t*)(sPl + oa + 8*RSV + 8);
#pragma unroll
            for (int nt = 0; nt < 8; nt++) {
                int ob = (wcP*64 + nt*8 + qr) * RSV + kb;
                bH[nt][0] = *(const uint32_t*)(sVh + ob);
                bH[nt][1] = *(const uint32_t*)(sVh + ob + 8);
                bL[nt][0] = *(const uint32_t*)(sVl + ob);
                bL[nt][1] = *(const uint32_t*)(sVl + ob + 8);
            }
#pragma unroll
            for (int nt = 0; nt < 8; nt++) mma_bf16(o[nt], aH, bH[nt]);
#pragma unroll
            for (int nt = 0; nt < 8; nt++) mma_bf16(o[nt], aH, bL[nt]);
#pragma unroll
            for (int nt = 0; nt < 8; nt++) mma_bf16(o[nt], aL, bH[nt]);
        }
    }

    int rA = wrP*16 + qr, rB = rA + 8;
    float i1 = 1.f / rowl[rA], i2 = 1.f / rowl[rB];
    int b = bh >> 4, h = bh & 15;
#pragma unroll
    for (int nt = 0; nt < 8; nt++) {
        int col = wcP*64 + nt*8 + kp;
        float2 v0 = { o[nt][0]*i1, o[nt][1]*i1 };
        *(float2*)&out[((size_t)(b*S_ + q0 + rA))*D_ + h*HD_ + col] = v0;
        float2 v1 = { o[nt][2]*i2, o[nt][3]*i2 };
        *(float2*)&out[((size_t)(b*S_ + q0 + rB))*D_ + h*HD_ + col] = v1;
    }
}

// ---------------------------------------------------------------------------
extern "C" void kernel_launch(void* const* d_in, const int* in_sizes, int n_in,
                              void* d_out, int out_size) {
    const float* hidden = (const float*)d_in[0];
    const float* w_qkv  = (const float*)d_in[1];
    const float* b_qkv  = (const float*)d_in[2];
    float* out = (float*)d_out;

    cudaFuncSetAttribute(attn_mma, cudaFuncAttributeMaxDynamicSharedMemorySize,
                         ATTN_SMEM);

    reset_flags<<<6, 256>>>();
    split_all<<<5120, 256>>>(hidden, w_qkv);
    qkv_mma<<<dim3(TX_, TY_), 256, GEMM_SMEM>>>(b_qkv);
    verify_tiles<<<TY_*TX_, 256>>>(hidden, w_qkv, b_qkv);
    qkv_fp32<<<dim3(TX_, TY_), 256>>>(hidden, w_qkv, b_qkv);

    int total = B_ * H_ * S_ * 64;
    qk_convert<<<(total + 255) / 256, 256>>>();
    v_convert<<<dim3(S_/32, HD_/32, B_*H_), dim3(32, 8)>>>();

    attn_mma<<<dim3(S_ / 64, B_ * H_), 256, ATTN_SMEM>>>(out);
}

// round 16
// speedup vs baseline: 4.0073x; 1.2692x over previous
#include <cuda_runtime.h>
#include <cuda_bf16.h>
#include <cstdint>

#define B_  4
#define S_  1024
#define D_  2048
#define H_  16
#define HD_ 128

#define MA_ (B_*S_)    // 4096
#define NA_ (3*D_)     // 6144
#define KA_ D_         // 2048

#define TX_ 48
#define TY_ 32

// Scratch (allocation-free rule)
__device__ float g_q[B_*H_*S_*HD_];
__device__ float g_k[B_*H_*S_*HD_];
__device__ float g_v[B_*H_*S_*HD_];
__device__ __align__(16) __nv_bfloat16 g_ah[(size_t)MA_*KA_];
__device__ __align__(16) __nv_bfloat16 g_al[(size_t)MA_*KA_];
__device__ __align__(16) __nv_bfloat16 g_wh[(size_t)NA_*KA_];
__device__ __align__(16) __nv_bfloat16 g_wl[(size_t)NA_*KA_];
// attention bf16 operands (q/k: [b,h,s,d]; v transposed: [b,h,d,s])
__device__ __align__(16) __nv_bfloat16 g_qh[B_*H_*S_*HD_];
__device__ __align__(16) __nv_bfloat16 g_ql[B_*H_*S_*HD_];
__device__ __align__(16) __nv_bfloat16 g_kh[B_*H_*S_*HD_];
__device__ __align__(16) __nv_bfloat16 g_kl[B_*H_*S_*HD_];
__device__ __align__(16) __nv_bfloat16 g_vth[B_*H_*S_*HD_];
__device__ __align__(16) __nv_bfloat16 g_vtl[B_*H_*S_*HD_];
__device__ int g_tilebad[TY_*TX_];

__device__ __forceinline__ void mma_bf16(float c[4], const uint32_t a[4],
                                         const uint32_t b[2]) {
    asm volatile("mma.sync.aligned.m16n8k16.row.col.f32.bf16.bf16.f32 "
        "{%0,%1,%2,%3}, {%4,%5,%6,%7}, {%8,%9}, {%0,%1,%2,%3};"
        : "+f"(c[0]), "+f"(c[1]), "+f"(c[2]), "+f"(c[3])
        : "r"(a[0]), "r"(a[1]), "r"(a[2]), "r"(a[3]), "r"(b[0]), "r"(b[1]));
}

__device__ __forceinline__ uint32_t smem_u32(const void* p) {
    uint32_t a;
    asm("{ .reg .u64 t; cvta.to.shared.u64 t, %1; cvt.u32.u64 %0, t; }"
        : "=r"(a) : "l"(p));
    return a;
}

__device__ __forceinline__ void ldm_x4(uint32_t addr, uint32_t f[4]) {
    asm volatile("ldmatrix.sync.aligned.m8n8.x4.shared.b16 {%0,%1,%2,%3}, [%4];"
        : "=r"(f[0]), "=r"(f[1]), "=r"(f[2]), "=r"(f[3]) : "r"(addr));
}

__device__ __forceinline__ void split4(float4 v, __nv_bfloat16* hp,
                                       __nv_bfloat16* lp, int off) {
    __nv_bfloat16 h0 = __float2bfloat16_rn(v.x);
    __nv_bfloat16 h1 = __float2bfloat16_rn(v.y);
    __nv_bfloat16 h2 = __float2bfloat16_rn(v.z);
    __nv_bfloat16 h3 = __float2bfloat16_rn(v.w);
    __nv_bfloat16 l0 = __float2bfloat16_rn(v.x - __bfloat162float(h0));
    __nv_bfloat16 l1 = __float2bfloat16_rn(v.y - __bfloat162float(h1));
    __nv_bfloat16 l2 = __float2bfloat16_rn(v.z - __bfloat162float(h2));
    __nv_bfloat16 l3 = __float2bfloat16_rn(v.w - __bfloat162float(h3));
    ((__nv_bfloat162*)hp)[2*off+0] = __halves2bfloat162(h0, h1);
    ((__nv_bfloat162*)hp)[2*off+1] = __halves2bfloat162(h2, h3);
    ((__nv_bfloat162*)lp)[2*off+0] = __halves2bfloat162(l0, l1);
    ((__nv_bfloat162*)lp)[2*off+1] = __halves2bfloat162(l2, l3);
}

// ---------------------------------------------------------------------------
__global__ void reset_flags() {
    int i = blockIdx.x * 256 + threadIdx.x;
    if (i < TY_*TX_) g_tilebad[i] = 0;
}

#define N4A (MA_*KA_/4)
__global__ __launch_bounds__(256) void split_all(const float* __restrict__ hidden,
                                                 const float* __restrict__ w) {
    int i4 = blockIdx.x * 256 + threadIdx.x;
    int base = i4 * 4;
    const float* src; __nv_bfloat16 *hp, *lp; int off;
    if (base < N4A) { src = hidden; hp = g_ah; lp = g_al; off = base; }
    else            { src = w;      hp = g_wh; lp = g_wl; off = base - N4A; }
    float4 v[4];
#pragma unroll
    for (int t = 0; t < 4; t++) v[t] = ((const float4*)src)[off + t];
#pragma unroll
    for (int t = 0; t < 4; t++) split4(v[t], hp, lp, off + t);
}

// ---------------------------------------------------------------------------
// bf16x3 QKV GEMM via mma.sync + ldmatrix.x4 fragment loads.
// Term-outer mma ordering (validated R11).
// ---------------------------------------------------------------------------
#define RS   40
#define ARR  (128*RS)
#define GEMM_SMEM (4*ARR*2)      // 40960 bytes

__global__ __launch_bounds__(256) void qkv_mma(const float* __restrict__ bias) {
    extern __shared__ __nv_bfloat16 sh[];
    uint32_t sb32 = smem_u32(sh);

    int tid = threadIdx.x;
    int wid = tid >> 5, lid = tid & 31;
    int bn = blockIdx.x * 128, bm = blockIdx.y * 128;
    int wm = wid & 1, wn = wid >> 1;
    int qr = lid >> 2;
    int kp = (lid & 3) * 2;

    const __nv_bfloat16* baseA_h = g_ah + (size_t)bm * KA_;
    const __nv_bfloat16* baseA_l = g_al + (size_t)bm * KA_;
    const __nv_bfloat16* baseW_h = g_wh + (size_t)bn * KA_;
    const __nv_bfloat16* baseW_l = g_wl + (size_t)bn * KA_;

    int ldr = tid >> 2, ldc = tid & 3;

    // ldmatrix per-lane address components
    int aRow = lid & 15;             // row within 16-row A fragment
    int aSel = (lid >> 4) & 1;       // k elems +8 (matrices 2,3)
    int bM   = lid >> 3;             // matrix index 0..3
    int bRow = (lid & 7) + ((bM >> 1) & 1) * 8;   // row within 16-row B pair
    int bSel = bM & 1;               // k elems +8

    float acc[4][4][4];
#pragma unroll
    for (int i = 0; i < 4; i++)
#pragma unroll
        for (int j = 0; j < 4; j++)
#pragma unroll
            for (int k = 0; k < 4; k++) acc[i][j][k] = 0.f;

    float4 stg[8];
#pragma unroll
    for (int t = 0; t < 2; t++) {
        int r = ldr + t * 64;
        size_t go = (size_t)r * KA_ + ldc * 8;
        stg[0*2+t] = *(const float4*)(baseA_h + go);
        stg[1*2+t] = *(const float4*)(baseA_l + go);
        stg[2*2+t] = *(const float4*)(baseW_h + go);
        stg[3*2+t] = *(const float4*)(baseW_l + go);
    }

    const int NITER = KA_ / 32;
    for (int it = 0; it < NITER; it++) {
        __syncthreads();
#pragma unroll
        for (int arr = 0; arr < 4; arr++)
#pragma unroll
            for (int t = 0; t < 2; t++) {
                int r = ldr + t * 64;
                *(float4*)(sh + arr*ARR + r*RS + ldc*8) = stg[arr*2 + t];
            }
        __syncthreads();
        if (it + 1 < NITER) {
            int k0 = (it + 1) * 32;
#pragma unroll
            for (int t = 0; t < 2; t++) {
                int r = ldr + t * 64;
                size_t go = (size_t)r * KA_ + k0 + ldc * 8;
                stg[0*2+t] = *(const float4*)(baseA_h + go);
                stg[1*2+t] = *(const float4*)(baseA_l + go);
                stg[2*2+t] = *(const float4*)(baseW_h + go);
                stg[3*2+t] = *(const float4*)(baseW_l + go);
            }
        }

#pragma unroll
        for (int ks = 0; ks < 2; ks++) {
            uint32_t aHf[4][4], aLf[4][4], bHf[4][2], bLf[4][2];
            // A fragments: one ldmatrix.x4 per (am, term)
#pragma unroll
            for (int am = 0; am < 4; am++) {
                uint32_t eo = (uint32_t)((wm*64 + am*16 + aRow) * RS
                                         + ks*16 + aSel*8) * 2;
                ldm_x4(sb32 + eo,            aHf[am]);
                ldm_x4(sb32 + ARR*2 + eo,    aLf[am]);
            }
            // B fragments: one ldmatrix.x4 per (nt-pair, term)
#pragma unroll
            for (int p2 = 0; p2 < 2; p2++) {
                uint32_t eo = (uint32_t)((wn*32 + p2*16 + bRow) * RS
                                         + ks*16 + bSel*8) * 2;
                uint32_t f[4];
                ldm_x4(sb32 + 2*ARR*2 + eo, f);
                bHf[p2*2+0][0] = f[0]; bHf[p2*2+0][1] = f[1];
                bHf[p2*2+1][0] = f[2]; bHf[p2*2+1][1] = f[3];
                ldm_x4(sb32 + 3*ARR*2 + eo, f);
                bLf[p2*2+0][0] = f[0]; bLf[p2*2+0][1] = f[1];
                bLf[p2*2+1][0] = f[2]; bLf[p2*2+1][1] = f[3];
            }
            // term-outer mma (consecutive mmas hit distinct accumulators)
#pragma unroll
            for (int am = 0; am < 4; am++)
#pragma unroll
                for (int nb = 0; nb < 4; nb++)
                    mma_bf16(acc[am][nb], aHf[am], bHf[nb]);
#pragma unroll
            for (int am = 0; am < 4; am++)
#pragma unroll
                for (int nb = 0; nb < 4; nb++)
                    mma_bf16(acc[am][nb], aHf[am], bLf[nb]);
#pragma unroll
            for (int am = 0; am < 4; am++)
#pragma unroll
                for (int nb = 0; nb < 4; nb++)
                    mma_bf16(acc[am][nb], aLf[am], bHf[nb]);
        }
    }

    int b = bm >> 10;
#pragma unroll
    for (int am = 0; am < 4; am++) {
        int s0 = (bm & 1023) + wm * 64 + am * 16 + qr;
#pragma unroll
        for (int nb = 0; nb < 4; nb++) {
            int n0    = bn + wn * 32 + nb * 8;
            int h     = n0 / 384;
            int inner = n0 - h * 384;
            int part  = inner >> 7;
            int dd    = (inner & 127) + kp;
            float* dst = (part == 0) ? g_q : (part == 1) ? g_k : g_v;
            float b0v = bias[n0 + kp], b1v = bias[n0 + kp + 1];
            size_t rb = ((size_t)(b * H_ + h) * S_);
            float2 v0 = { acc[am][nb][0] + b0v, acc[am][nb][1] + b1v };
            *(float2*)&dst[(rb + s0) * HD_ + dd] = v0;
            float2 v1 = { acc[am][nb][2] + b0v, acc[am][nb][3] + b1v };
            *(float2*)&dst[(rb + s0 + 8) * HD_ + dd] = v1;
        }
    }
}

// ---------------------------------------------------------------------------
// Light verify: 1 sample per tile, block-wide coalesced dot (256 thr).
// ---------------------------------------------------------------------------
__global__ __launch_bounds__(256) void verify_tiles(const float* __restrict__ hidden,
                                                    const float* __restrict__ w,
                                                    const float* __restrict__ bias) {
    __shared__ float red[8];
    int tile = blockIdx.x;
    int ty = tile / TX_, tx = tile - ty * TX_;
    int m = ty * 128 + ((tile*37 + 11) & 127);
    int n = tx * 128 + ((tile*53 + 7) & 127);
    int t = threadIdx.x;
    const float* hr = hidden + (size_t)m * KA_;
    const float* wr = w + (size_t)n * KA_;
    float p = 0.f;
#pragma unroll
    for (int k = t; k < KA_; k += 256) p += hr[k] * wr[k];
#pragma unroll
    for (int off = 16; off > 0; off >>= 1)
        p += __shfl_down_sync(0xffffffffu, p, off);
    if ((t & 31) == 0) red[t >> 5] = p;
    __syncthreads();
    if (t == 0) {
        float ref = bias[n];
#pragma unroll
        for (int i = 0; i < 8; i++) ref += red[i];
        int b = m >> 10, s = m & 1023;
        int h = n / 384, inner = n - h*384, part = inner >> 7, dd = inner & 127;
        const float* src = (part == 0) ? g_q : (part == 1) ? g_k : g_v;
        float got = src[((size_t)(b*H_ + h)*S_ + s)*HD_ + dd];
        if (!(fabsf(got - ref) <= 0.02f + 0.01f*fabsf(ref)))
            g_tilebad[tile] = 1;
    }
}

// ---------------------------------------------------------------------------
// Per-tile fp32 repair (no-op where verified).
// ---------------------------------------------------------------------------
__global__ __launch_bounds__(256) void qkv_fp32(const float* __restrict__ A,
                                                const float* __restrict__ W,
                                                const float* __restrict__ bias) {
    if (!g_tilebad[blockIdx.y*TX_ + blockIdx.x]) return;
    __shared__ float As[8][128];
    __shared__ float Bs[8][128];
    int tid = threadIdx.x;
    int bm = blockIdx.y * 128, bn = blockIdx.x * 128;
    int lr = tid >> 1;
    int lk = (tid & 1) * 4;
    const float* Ap = A + (size_t)(bm + lr) * D_ + lk;
    const float* Wp = W + (size_t)(bn + lr) * D_ + lk;
    int tx = tid & 15, ty = tid >> 4;

    float acc[8][8];
#pragma unroll
    for (int i = 0; i < 8; i++)
#pragma unroll
        for (int j = 0; j < 8; j++) acc[i][j] = 0.f;

    for (int k0 = 0; k0 < D_; k0 += 8) {
        float4 a4 = *(const float4*)(Ap + k0);
        float4 b4 = *(const float4*)(Wp + k0);
        __syncthreads();
        As[lk+0][lr] = a4.x; As[lk+1][lr] = a4.y; As[lk+2][lr] = a4.z; As[lk+3][lr] = a4.w;
        Bs[lk+0][lr] = b4.x; Bs[lk+1][lr] = b4.y; Bs[lk+2][lr] = b4.z; Bs[lk+3][lr] = b4.w;
        __syncthreads();
#pragma unroll
        for (int kk = 0; kk < 8; kk++) {
            float4 a0 = *(const float4*)&As[kk][ty*4];
            float4 a1 = *(const float4*)&As[kk][ty*4 + 64];
            float4 b0 = *(const float4*)&Bs[kk][tx*4];
            float4 b1 = *(const float4*)&Bs[kk][tx*4 + 64];
            float ra[8] = {a0.x,a0.y,a0.z,a0.w,a1.x,a1.y,a1.z,a1.w};
            float rb[8] = {b0.x,b0.y,b0.z,b0.w,b1.x,b1.y,b1.z,b1.w};
#pragma unroll
            for (int i = 0; i < 8; i++)
#pragma unroll
                for (int j = 0; j < 8; j++)
                    acc[i][j] += ra[i] * rb[j];
        }
    }

#pragma unroll
    for (int i = 0; i < 8; i++) {
        int m = bm + ((i < 4) ? ty*4 + i : 64 + ty*4 + (i - 4));
        int b = m >> 10, s = m & 1023;
#pragma unroll
        for (int j = 0; j < 8; j++) {
            int n = bn + ((j < 4) ? tx*4 + j : 64 + tx*4 + (j - 4));
            float v = acc[i][j] + bias[n];
            int h = n / 384;
            int inner = n - h * 384;
            int part = inner >> 7;
            int dd = inner & 127;
            float* dst = (part == 0) ? g_q : (part == 1) ? g_k : g_v;
            dst[((size_t)((b*H_ + h)*S_ + s)) * HD_ + dd] = v;
        }
    }
}

// ---------------------------------------------------------------------------
// q/k: RoPE + (q: 1/sqrt(hd) scale) + bf16 hi/lo split.
// ---------------------------------------------------------------------------
__global__ __launch_bounds__(256) void qk_convert() {
    int i = blockIdx.x * blockDim.x + threadIdx.x;
    const int total = B_ * H_ * S_ * 64;
    if (i >= total) return;
    int j = i & 63;
    int bhs = i >> 6;
    int s = bhs & (S_ - 1);
    float ang = (float)s * exp2f(-(float)j * (13.287712379549449f / 64.f));
    float sn, c;
    sincosf(ang, &sn, &c);
    const float scale = 0.08838834764831845f;

    {
        const float* p = g_q + (size_t)bhs * HD_;
        float x1 = p[j], x2 = p[j + 64];
        float r1 = (x1 * c - x2 * sn) * scale;
        float r2 = (x2 * c + x1 * sn) * scale;
        __nv_bfloat16 h1 = __float2bfloat16_rn(r1);
        __nv_bfloat16 h2 = __float2bfloat16_rn(r2);
        g_qh[(size_t)bhs*HD_ + j]      = h1;
        g_qh[(size_t)bhs*HD_ + j + 64] = h2;
        g_ql[(size_t)bhs*HD_ + j]      = __float2bfloat16_rn(r1 - __bfloat162float(h1));
        g_ql[(size_t)bhs*HD_ + j + 64] = __float2bfloat16_rn(r2 - __bfloat162float(h2));
    }
    {
        const float* p = g_k + (size_t)bhs * HD_;
        float x1 = p[j], x2 = p[j + 64];
        float r1 = x1 * c - x2 * sn;
        float r2 = x2 * c + x1 * sn;
        __nv_bfloat16 h1 = __float2bfloat16_rn(r1);
        __nv_bfloat16 h2 = __float2bfloat16_rn(r2);
        g_kh[(size_t)bhs*HD_ + j]      = h1;
        g_kh[(size_t)bhs*HD_ + j + 64] = h2;
        g_kl[(size_t)bhs*HD_ + j]      = __float2bfloat16_rn(r1 - __bfloat162float(h1));
        g_kl[(size_t)bhs*HD_ + j + 64] = __float2bfloat16_rn(r2 - __bfloat162float(h2));
    }
}

// ---------------------------------------------------------------------------
// v: transpose [s][d] -> [d][s] per (b,h), bf16 hi/lo split.
// ---------------------------------------------------------------------------
__global__ void v_convert(void) {
    __shared__ float tile[32][33];
    int bh = blockIdx.z;
    int s0 = blockIdx.x * 32, d0 = blockIdx.y * 32;
    const float* vb = g_v + (size_t)bh * S_ * HD_;
#pragma unroll
    for (int i = 0; i < 32; i += 8)
        tile[threadIdx.y + i][threadIdx.x] =
            vb[(size_t)(s0 + threadIdx.y + i) * HD_ + d0 + threadIdx.x];
    __syncthreads();
#pragma unroll
    for (int i = 0; i < 32; i += 8) {
        int d = d0 + threadIdx.y + i, sx = s0 + threadIdx.x;
        float v = tile[threadIdx.x][threadIdx.y + i];
        __nv_bfloat16 h = __float2bfloat16_rn(v);
        size_t o = ((size_t)bh * HD_ + d) * S_ + sx;
        g_vth[o] = h;
        g_vtl[o] = __float2bfloat16_rn(v - __bfloat162float(h));
    }
}

// ---------------------------------------------------------------------------
// Causal flash attention via mma.sync bf16x3 (validated R12) with
// 4-threads-per-row parallel softmax.
// ---------------------------------------------------------------------------
#define RSA 136
#define RSV 72
#define ATTN_SMEM 158976

__global__ __launch_bounds__(256) void attn_mma(float* __restrict__ out) {
    extern __shared__ char smraw[];
    __nv_bfloat16* sQh = (__nv_bfloat16*)smraw;
    __nv_bfloat16* sQl = sQh + 64*RSA;
    __nv_bfloat16* sKh = sQl + 64*RSA;
    __nv_bfloat16* sKl = sKh + 64*RSA;
    __nv_bfloat16* sVh = sKl + 64*RSA;
    __nv_bfloat16* sVl = sVh + 128*RSV;
    __nv_bfloat16* sPh = sVl + 128*RSV;
    __nv_bfloat16* sPl = sPh + 64*RSV;
    float* ScA  = (float*)(sPl + 64*RSV);
    float* ScB  = ScA + 64*65;
    float* rowm = ScB + 64*65;
    float* rowl = rowm + 64;
    float* corr = rowl + 64;

    int tid = threadIdx.x, wid = tid >> 5, lid = tid & 31;
    int qt = blockIdx.x, bh = blockIdx.y, q0 = qt * 64;
    int qr = lid >> 2, kp = (lid & 3) * 2;

    const __nv_bfloat16* Qhg = g_qh + (size_t)(bh*S_ + q0) * HD_;
    const __nv_bfloat16* Qlg = g_ql + (size_t)(bh*S_ + q0) * HD_;

#pragma unroll
    for (int t = 0; t < 4; t++) {
        int ch = tid + t * 256;
        int r = ch >> 4, c8 = (ch & 15) * 8;
        *(float4*)(sQh + r*RSA + c8) = *(const float4*)(Qhg + r*HD_ + c8);
        *(float4*)(sQl + r*RSA + c8) = *(const float4*)(Qlg + r*HD_ + c8);
    }
    if (tid < 64) { rowm[tid] = -1e30f; rowl[tid] = 0.f; }

    float o[8][4];
#pragma unroll
    for (int i = 0; i < 8; i++)
#pragma unroll
        for (int j = 0; j < 4; j++) o[i][j] = 0.f;

    int wrS = wid & 3, gS = wid >> 2;
    int wrP = wid & 3, wcP = wid >> 2;
    float* ScW = gS ? ScB : ScA;

    for (int kt = 0; kt <= qt; kt++) {
        int k0 = kt * 64;
        __syncthreads();
#pragma unroll
        for (int t = 0; t < 4; t++) {
            int ch = tid + t * 256;
            int r = ch >> 4, c8 = (ch & 15) * 8;
            size_t go = (size_t)(bh*S_ + k0 + r) * HD_ + c8;
            *(float4*)(sKh + r*RSA + c8) = *(const float4*)(g_kh + go);
            *(float4*)(sKl + r*RSA + c8) = *(const float4*)(g_kl + go);
        }
#pragma unroll
        for (int t = 0; t < 4; t++) {
            int ch = tid + t * 256;
            int r = ch >> 3, c8 = (ch & 7) * 8;
            size_t go = ((size_t)bh*HD_ + r) * S_ + k0 + c8;
            *(float4*)(sVh + r*RSV + c8) = *(const float4*)(g_vth + go);
            *(float4*)(sVl + r*RSV + c8) = *(const float4*)(g_vtl + go);
        }
        __syncthreads();

        // ---- QK^T ----
        float sc[8][4];
#pragma unroll
        for (int i = 0; i < 8; i++)
#pragma unroll
            for (int j = 0; j < 4; j++) sc[i][j] = 0.f;

#pragma unroll
        for (int ks = 0; ks < 4; ks++) {
            int kb = gS*64 + ks*16 + kp;
            uint32_t aH[4], aL[4], bH[8][2], bL[8][2];
            int oa = (wrS*16 + qr) * RSA + kb;
            aH[0] = *(const uint32_t*)(sQh + oa);
            aH[1] = *(const uint32_t*)(sQh + oa + 8*RSA);
            aH[2] = *(const uint32_t*)(sQh + oa + 8);
            aH[3] = *(const uint32_t*)(sQh + oa + 8*RSA + 8);
            aL[0] = *(const uint32_t*)(sQl + oa);
            aL[1] = *(const uint32_t*)(sQl + oa + 8*RSA);
            aL[2] = *(const uint32_t*)(sQl + oa + 8);
            aL[3] = *(const uint32_t*)(sQl + oa + 8*RSA + 8);
#pragma unroll
            for (int nt = 0; nt < 8; nt++) {
                int ob = (nt*8 + qr) * RSA + kb;
                bH[nt][0] = *(const uint32_t*)(sKh + ob);
                bH[nt][1] = *(const uint32_t*)(sKh + ob + 8);
                bL[nt][0] = *(const uint32_t*)(sKl + ob);
                bL[nt][1] = *(const uint32_t*)(sKl + ob + 8);
            }
#pragma unroll
            for (int nt = 0; nt < 8; nt++) mma_bf16(sc[nt], aH, bH[nt]);
#pragma unroll
            for (int nt = 0; nt < 8; nt++) mma_bf16(sc[nt], aH, bL[nt]);
#pragma unroll
            for (int nt = 0; nt < 8; nt++) mma_bf16(sc[nt], aL, bH[nt]);
        }
#pragma unroll
        for (int nt = 0; nt < 8; nt++)
#pragma unroll
            for (int t = 0; t < 4; t++) {
                int r = wrS*16 + qr + ((t >= 2) ? 8 : 0);
                int c = nt*8 + kp + (t & 1);
                ScW[r*65 + c] = sc[nt][t];
            }
        __syncthreads();

        // ---- parallel softmax: 4 threads per row, 16 cols each ----
        {
            int r = tid >> 2, ln = tid & 3;
            bool diag = (kt == qt);
            float mo = rowm[r];
            float mx = mo;
            float vbuf[16];
#pragma unroll
            for (int cc = 0; cc < 16; cc++) {
                int c = ln*16 + cc;
                float v = (diag && c > r) ? -1e30f : ScA[r*65+c] + ScB[r*65+c];
                vbuf[cc] = v;
                mx = fmaxf(mx, v);
            }
            mx = fmaxf(mx, __shfl_xor_sync(0xffffffffu, mx, 1));
            mx = fmaxf(mx, __shfl_xor_sync(0xffffffffu, mx, 2));
            float su = 0.f;
#pragma unroll
            for (int cc = 0; cc < 16; cc++) {
                int c = ln*16 + cc;
                float p = __expf(vbuf[cc] - mx);
                su += p;
                __nv_bfloat16 ph = __float2bfloat16_rn(p);
                sPh[r*RSV + c] = ph;
                sPl[r*RSV + c] = __float2bfloat16_rn(p - __bfloat162float(ph));
            }
            su += __shfl_xor_sync(0xffffffffu, su, 1);
            su += __shfl_xor_sync(0xffffffffu, su, 2);
            if (ln == 0) {
                float co = __expf(mo - mx);
                rowl[r] = rowl[r] * co + su;
                rowm[r] = mx;
                corr[r] = co;
            }
        }
        __syncthreads();

        // ---- O = O*corr + P V ----
        float co1 = corr[wrP*16 + qr], co2 = corr[wrP*16 + qr + 8];
#pragma unroll
        for (int nt = 0; nt < 8; nt++) {
            o[nt][0] *= co1; o[nt][1] *= co1;
            o[nt][2] *= co2; o[nt][3] *= co2;
        }
#pragma unroll
        for (int ks = 0; ks < 4; ks++) {
            int kb = ks*16 + kp;
            uint32_t aH[4], aL[4], bH[8][2], bL[8][2];
            int oa = (wrP*16 + qr) * RSV + kb;
            aH[0] = *(const uint32_t*)(sPh + oa);
            aH[1] = *(const uint32_t*)(sPh + oa + 8*RSV);
            aH[2] = *(const uint32_t*)(sPh + oa + 8);
            aH[3] = *(const uint32_t*)(sPh + oa + 8*RSV + 8);
            aL[0] = *(const uint32_t*)(sPl + oa);
            aL[1] = *(const uint32_t*)(sPl + oa + 8*RSV);
            aL[2] = *(const uint32_t*)(sPl + oa + 8);
            aL[3] = *(const uint32_t*)(sPl + oa + 8*RSV + 8);
#pragma unroll
            for (int nt = 0; nt < 8; nt++) {
                int ob = (wcP*64 + nt*8 + qr) * RSV + kb;
                bH[nt][0] = *(const uint32_t*)(sVh + ob);
                bH[nt][1] = *(const uint32_t*)(sVh + ob + 8);
                bL[nt][0] = *(const uint32_t*)(sVl + ob);
                bL[nt][1] = *(const uint32_t*)(sVl + ob + 8);
            }
#pragma unroll
            for (int nt = 0; nt < 8; nt++) mma_bf16(o[nt], aH, bH[nt]);
#pragma unroll
            for (int nt = 0; nt < 8; nt++) mma_bf16(o[nt], aH, bL[nt]);
#pragma unroll
            for (int nt = 0; nt < 8; nt++) mma_bf16(o[nt], aL, bH[nt]);
        }
    }

    int rA = wrP*16 + qr, rB = rA + 8;
    float i1 = 1.f / rowl[rA], i2 = 1.f / rowl[rB];
    int b = bh >> 4, h = bh & 15;
#pragma unroll
    for (int nt = 0; nt < 8; nt++) {
        int col = wcP*64 + nt*8 + kp;
        float2 v0 = { o[nt][0]*i1, o[nt][1]*i1 };
        *(float2*)&out[((size_t)(b*S_ + q0 + rA))*D_ + h*HD_ + col] = v0;
        float2 v1 = { o[nt][2]*i2, o[nt][3]*i2 };
        *(float2*)&out[((size_t)(b*S_ + q0 + rB))*D_ + h*HD_ + col] = v1;
    }
}

// ---------------------------------------------------------------------------
extern "C" void kernel_launch(void* const* d_in, const int* in_sizes, int n_in,
                              void* d_out, int out_size) {
    const float* hidden = (const float*)d_in[0];
    const float* w_qkv  = (const float*)d_in[1];
    const float* b_qkv  = (const float*)d_in[2];
    float* out = (float*)d_out;

    cudaFuncSetAttribute(attn_mma, cudaFuncAttributeMaxDynamicSharedMemorySize,
                         ATTN_SMEM);

    reset_flags<<<6, 256>>>();
    split_all<<<5120, 256>>>(hidden, w_qkv);
    qkv_mma<<<dim3(TX_, TY_), 256, GEMM_SMEM>>>(b_qkv);
    verify_tiles<<<TY_*TX_, 256>>>(hidden, w_qkv, b_qkv);
    qkv_fp32<<<dim3(TX_, TY_), 256>>>(hidden, w_qkv, b_qkv);

    int total = B_ * H_ * S_ * 64;
    qk_convert<<<(total + 255) / 256, 256>>>();
    v_convert<<<dim3(S_/32, HD_/32, B_*H_), dim3(32, 8)>>>();

    attn_mma<<<dim3(S_ / 64, B_ * H_), 256, ATTN_SMEM>>>(out);
}